// round 1
// baseline (speedup 1.0000x reference)
#include <cuda_runtime.h>
#include <math.h>

// Problem shape constants
#define B_ 2
#define S_ 2048
#define D_ 1024
#define H_ 16
#define HD_ 64

// ---------------- scratch (static __device__ arrays; no allocation) ----------------
__device__ float g_ada[B_ * 6 * D_];                       // [2,6144]
__device__ float g_h[(size_t)B_ * S_ * D_];                // [4096,1024] LN+mod output / reuse
__device__ float g_qkv[(size_t)B_ * S_ * 3 * D_];          // [4096,3072]
__device__ float g_q[(size_t)B_ * H_ * S_ * HD_];          // [B,H,S,HD]
__device__ float g_k[(size_t)B_ * H_ * S_ * HD_];
__device__ float g_v[(size_t)B_ * H_ * S_ * HD_];
__device__ float g_scores[(size_t)B_ * H_ * S_ * S_];      // 536MB
__device__ float g_attn[(size_t)B_ * H_ * S_ * HD_];       // [B,H,S,HD]
__device__ float g_attn2[(size_t)B_ * S_ * D_];            // [B,S,D]
__device__ float g_x1[(size_t)B_ * S_ * D_];
__device__ float g_mlp[(size_t)B_ * S_ * 4 * D_];          // [4096,4096]
__device__ float g_t[(size_t)B_ * S_ * D_];

// ---------------- generic NT GEMM: C[M,N] = alpha * A[M,K] @ B[N,K]^T ----------------
// Requires M%128==0, N%128==0, K%16==0, lda/ldb/ldc %4==0.
__global__ void __launch_bounds__(256) gemm_nt(
    const float* __restrict__ A, const float* __restrict__ B, float* __restrict__ C,
    int M, int N, int K, int lda, int ldb, int ldc, float alpha,
    long sA, long sB, long sC)
{
    A += (long)blockIdx.z * sA;
    B += (long)blockIdx.z * sB;
    C += (long)blockIdx.z * sC;
    __shared__ float As[16][132];
    __shared__ float Bs[16][132];
    const int tid = threadIdx.x;
    const int tx = tid & 15;
    const int ty = tid >> 4;
    const int rowBase = blockIdx.y * 128;
    const int colBase = blockIdx.x * 128;

    float acc[8][8];
#pragma unroll
    for (int i = 0; i < 8; i++)
#pragma unroll
        for (int j = 0; j < 8; j++) acc[i][j] = 0.f;

    for (int k0 = 0; k0 < K; k0 += 16) {
#pragma unroll
        for (int s = 0; s < 2; s++) {
            int slot = tid + s * 256;           // 0..511 float4 slots
            int r = slot >> 2;
            int c4 = (slot & 3) << 2;
            float4 va = *reinterpret_cast<const float4*>(&A[(long)(rowBase + r) * lda + k0 + c4]);
            As[c4 + 0][r] = va.x; As[c4 + 1][r] = va.y; As[c4 + 2][r] = va.z; As[c4 + 3][r] = va.w;
            float4 vb = *reinterpret_cast<const float4*>(&B[(long)(colBase + r) * ldb + k0 + c4]);
            Bs[c4 + 0][r] = vb.x; Bs[c4 + 1][r] = vb.y; Bs[c4 + 2][r] = vb.z; Bs[c4 + 3][r] = vb.w;
        }
        __syncthreads();
#pragma unroll
        for (int kk = 0; kk < 16; kk++) {
            float4 a0 = *reinterpret_cast<const float4*>(&As[kk][ty * 8]);
            float4 a1 = *reinterpret_cast<const float4*>(&As[kk][ty * 8 + 4]);
            float4 b0 = *reinterpret_cast<const float4*>(&Bs[kk][tx * 8]);
            float4 b1 = *reinterpret_cast<const float4*>(&Bs[kk][tx * 8 + 4]);
            float a[8] = {a0.x, a0.y, a0.z, a0.w, a1.x, a1.y, a1.z, a1.w};
            float b[8] = {b0.x, b0.y, b0.z, b0.w, b1.x, b1.y, b1.z, b1.w};
#pragma unroll
            for (int i = 0; i < 8; i++)
#pragma unroll
                for (int j = 0; j < 8; j++) acc[i][j] = fmaf(a[i], b[j], acc[i][j]);
        }
        __syncthreads();
    }
#pragma unroll
    for (int i = 0; i < 8; i++) {
        long row = rowBase + ty * 8 + i;
#pragma unroll
        for (int j = 0; j < 8; j += 4) {
            float4 v = make_float4(acc[i][j] * alpha, acc[i][j + 1] * alpha,
                                   acc[i][j + 2] * alpha, acc[i][j + 3] * alpha);
            *reinterpret_cast<float4*>(&C[row * ldc + colBase + tx * 8 + j]) = v;
        }
    }
}

// ---------------- NN GEMM for P@V: C[M,64] = A[M,K] @ B[K,64], ldb=ldc=64 ----------------
__global__ void __launch_bounds__(256) gemm_nn_pv(
    const float* __restrict__ A, const float* __restrict__ B, float* __restrict__ C,
    int M, int K, int lda, long sA, long sB, long sC)
{
    A += (long)blockIdx.z * sA;
    B += (long)blockIdx.z * sB;
    C += (long)blockIdx.z * sC;
    __shared__ float As[16][132];
    __shared__ float Bs[16][68];
    const int tid = threadIdx.x;
    const int tx = tid & 15;   // col = tx*4
    const int ty = tid >> 4;   // row = ty*8
    const int rowBase = blockIdx.y * 128;

    float acc[8][4];
#pragma unroll
    for (int i = 0; i < 8; i++)
#pragma unroll
        for (int j = 0; j < 4; j++) acc[i][j] = 0.f;

    for (int k0 = 0; k0 < K; k0 += 16) {
#pragma unroll
        for (int s = 0; s < 2; s++) {
            int slot = tid + s * 256;
            int r = slot >> 2;
            int c4 = (slot & 3) << 2;
            float4 va = *reinterpret_cast<const float4*>(&A[(long)(rowBase + r) * lda + k0 + c4]);
            As[c4 + 0][r] = va.x; As[c4 + 1][r] = va.y; As[c4 + 2][r] = va.z; As[c4 + 3][r] = va.w;
        }
        {
            int r = tid >> 4;            // 0..15 (k row)
            int c4 = (tid & 15) << 2;    // 0..60
            float4 vb = *reinterpret_cast<const float4*>(&B[(long)(k0 + r) * 64 + c4]);
            *reinterpret_cast<float4*>(&Bs[r][c4]) = vb;
        }
        __syncthreads();
#pragma unroll
        for (int kk = 0; kk < 16; kk++) {
            float4 a0 = *reinterpret_cast<const float4*>(&As[kk][ty * 8]);
            float4 a1 = *reinterpret_cast<const float4*>(&As[kk][ty * 8 + 4]);
            float4 bb = *reinterpret_cast<const float4*>(&Bs[kk][tx * 4]);
            float a[8] = {a0.x, a0.y, a0.z, a0.w, a1.x, a1.y, a1.z, a1.w};
            float b[4] = {bb.x, bb.y, bb.z, bb.w};
#pragma unroll
            for (int i = 0; i < 8; i++)
#pragma unroll
                for (int j = 0; j < 4; j++) acc[i][j] = fmaf(a[i], b[j], acc[i][j]);
        }
        __syncthreads();
    }
#pragma unroll
    for (int i = 0; i < 8; i++) {
        long row = rowBase + ty * 8 + i;
        float4 v = make_float4(acc[i][0], acc[i][1], acc[i][2], acc[i][3]);
        *reinterpret_cast<float4*>(&C[row * 64 + tx * 4]) = v;
    }
}

// ---------------- adaLN: ada[b,j] = c[b,:] @ ada_w[j,:] + ada_b[j] ----------------
__global__ void __launch_bounds__(256) ada_kernel(
    const float* __restrict__ c, const float* __restrict__ w,
    const float* __restrict__ bias, float* __restrict__ out)
{
    int warp = (blockIdx.x * blockDim.x + threadIdx.x) >> 5;
    int lane = threadIdx.x & 31;
    if (warp >= 6 * D_) return;
    const float* wr = w + (long)warp * D_;
    float s0 = 0.f, s1 = 0.f;
    for (int d = lane; d < D_; d += 32) {
        float wv = wr[d];
        s0 += c[d] * wv;
        s1 += c[D_ + d] * wv;
    }
#pragma unroll
    for (int o = 16; o > 0; o >>= 1) {
        s0 += __shfl_down_sync(0xffffffffu, s0, o);
        s1 += __shfl_down_sync(0xffffffffu, s1, o);
    }
    if (lane == 0) {
        out[warp] = s0 + bias[warp];
        out[6 * D_ + warp] = s1 + bias[warp];
    }
}

// ---------------- LayerNorm + modulate ----------------
__global__ void __launch_bounds__(256) ln_mod_kernel(
    const float* __restrict__ x, const float* __restrict__ w,
    const float* __restrict__ ada, int shOff, int scOff, float* __restrict__ h)
{
    int r = blockIdx.x;       // 0..4095 row = (b,s)
    int b = r >> 11;
    const float* xr = x + (long)r * D_;
    int tid = threadIdx.x;
    float s = 0.f, ss = 0.f;
    float vals[4];
#pragma unroll
    for (int i = 0; i < 4; i++) {
        float v = xr[tid + i * 256];
        vals[i] = v; s += v; ss += v * v;
    }
    __shared__ float rs[256], rss[256];
    rs[tid] = s; rss[tid] = ss;
    __syncthreads();
    for (int st = 128; st > 0; st >>= 1) {
        if (tid < st) { rs[tid] += rs[tid + st]; rss[tid] += rss[tid + st]; }
        __syncthreads();
    }
    float mean = rs[0] * (1.f / D_);
    float var = rss[0] * (1.f / D_) - mean * mean;
    float inv = rsqrtf(var + 1e-5f);
    const float* sh = ada + b * 6 * D_ + shOff;
    const float* sc = ada + b * 6 * D_ + scOff;
#pragma unroll
    for (int i = 0; i < 4; i++) {
        int d = tid + i * 256;
        h[(long)r * D_ + d] = (vals[i] - mean) * inv * w[d] * (1.f + sc[d]) + sh[d];
    }
}

// ---------------- repack qkv [B,S,3,H,HD] -> q/k/v [B,H,S,HD] ----------------
__global__ void repack_qkv(const float* __restrict__ qkv,
                           float* __restrict__ q, float* __restrict__ k, float* __restrict__ v)
{
    long idx = (long)blockIdx.x * 256 + threadIdx.x;
    if (idx >= (long)B_ * H_ * S_ * HD_) return;
    long t = idx;
    int hd = t & 63; t >>= 6;
    int s = t & 2047; t >>= 11;
    int h = t & 15; t >>= 4;
    int b = (int)t;
    long src = ((long)(b * S_ + s) * 3) * D_ + h * 64 + hd;
    q[idx] = qkv[src];
    k[idx] = qkv[src + D_];
    v[idx] = qkv[src + 2 * D_];
}

// ---------------- unpack attn [B,H,S,HD] -> [B,S,D] ----------------
__global__ void unpack_attn(const float* __restrict__ a, float* __restrict__ o)
{
    long idx = (long)blockIdx.x * 256 + threadIdx.x;   // layout (b,s,h,hd)
    if (idx >= (long)B_ * S_ * D_) return;
    long t = idx;
    int hd = t & 63; t >>= 6;
    int h = t & 15; t >>= 4;
    int s = t & 2047; t >>= 11;
    int b = (int)t;
    long src = ((long)(b * H_ + h) * S_ + s) * 64 + hd;
    o[idx] = a[src];
}

// ---------------- row softmax over 2048 ----------------
__global__ void __launch_bounds__(256) softmax_kernel(float* __restrict__ scp)
{
    long row = blockIdx.x;
    float* p = scp + row * (long)S_;
    __shared__ float buf[S_];
    __shared__ float red[256];
    int tid = threadIdx.x;
    float m = -INFINITY;
    for (int i = tid; i < S_; i += 256) {
        float v = p[i]; buf[i] = v; m = fmaxf(m, v);
    }
    red[tid] = m;
    __syncthreads();
    for (int s = 128; s > 0; s >>= 1) {
        if (tid < s) red[tid] = fmaxf(red[tid], red[tid + s]);
        __syncthreads();
    }
    m = red[0];
    __syncthreads();
    float sum = 0.f;
    for (int i = tid; i < S_; i += 256) {
        float e = __expf(buf[i] - m);
        buf[i] = e; sum += e;
    }
    red[tid] = sum;
    __syncthreads();
    for (int s = 128; s > 0; s >>= 1) {
        if (tid < s) red[tid] += red[tid + s];
        __syncthreads();
    }
    float inv = 1.f / red[0];
    for (int i = tid; i < S_; i += 256) p[i] = buf[i] * inv;
}

// ---------------- residual 1: x1 = x + g_msa * proj ----------------
__global__ void resid1_kernel(const float* __restrict__ x, const float* __restrict__ proj,
                              const float* __restrict__ ada, float* __restrict__ x1)
{
    long idx = (long)blockIdx.x * 256 + threadIdx.x;
    if (idx >= (long)B_ * S_ * D_) return;
    int d = (int)(idx & (D_ - 1));
    int b = (int)(idx >> 21);   // / (S_*D_)
    x1[idx] = x[idx] + ada[b * 6 * D_ + 2 * D_ + d] * proj[idx];
}

// ---------------- bias + gelu(tanh) in place ----------------
__global__ void bias_gelu_kernel(float* __restrict__ m, const float* __restrict__ b1)
{
    long idx = (long)blockIdx.x * 256 + threadIdx.x;
    if (idx >= (long)B_ * S_ * 4 * D_) return;
    int col = (int)(idx & (4 * D_ - 1));
    float v = m[idx] + b1[col];
    float u = 0.7978845608028654f * (v + 0.044715f * v * v * v);
    m[idx] = 0.5f * v * (1.f + tanhf(u));
}

// ---------------- final: out = x1 + g_mlp * (t + b2) ----------------
__global__ void final_kernel(const float* __restrict__ x1, const float* __restrict__ t,
                             const float* __restrict__ b2, const float* __restrict__ ada,
                             float* __restrict__ out)
{
    long idx = (long)blockIdx.x * 256 + threadIdx.x;
    if (idx >= (long)B_ * S_ * D_) return;
    int d = (int)(idx & (D_ - 1));
    int b = (int)(idx >> 21);
    out[idx] = x1[idx] + ada[b * 6 * D_ + 5 * D_ + d] * (t[idx] + b2[d]);
}

// ---------------- launch ----------------
extern "C" void kernel_launch(void* const* d_in, const int* in_sizes, int n_in,
                              void* d_out, int out_size)
{
    (void)in_sizes; (void)n_in; (void)out_size;
    const float* x       = (const float*)d_in[0];
    // d_in[1]=cos, d_in[2]=sin: unused by reference
    const float* c       = (const float*)d_in[3];
    const float* norm1_w = (const float*)d_in[4];
    const float* w_qkv   = (const float*)d_in[5];
    const float* w_out   = (const float*)d_in[6];
    const float* norm2_w = (const float*)d_in[7];
    const float* mlp_w1  = (const float*)d_in[8];
    const float* mlp_b1  = (const float*)d_in[9];
    const float* mlp_w2  = (const float*)d_in[10];
    const float* mlp_b2  = (const float*)d_in[11];
    const float* ada_w   = (const float*)d_in[12];
    const float* ada_b   = (const float*)d_in[13];
    float* out = (float*)d_out;

    float *ada, *h, *qkv, *q, *k, *v, *sc, *attn, *attn2, *x1, *mlp, *t;
    cudaGetSymbolAddress((void**)&ada,   g_ada);
    cudaGetSymbolAddress((void**)&h,     g_h);
    cudaGetSymbolAddress((void**)&qkv,   g_qkv);
    cudaGetSymbolAddress((void**)&q,     g_q);
    cudaGetSymbolAddress((void**)&k,     g_k);
    cudaGetSymbolAddress((void**)&v,     g_v);
    cudaGetSymbolAddress((void**)&sc,    g_scores);
    cudaGetSymbolAddress((void**)&attn,  g_attn);
    cudaGetSymbolAddress((void**)&attn2, g_attn2);
    cudaGetSymbolAddress((void**)&x1,    g_x1);
    cudaGetSymbolAddress((void**)&mlp,   g_mlp);
    cudaGetSymbolAddress((void**)&t,     g_t);

    const long nBSD = (long)B_ * S_ * D_;          // 4194304
    const long nQKV = (long)B_ * H_ * S_ * HD_;    // 4194304
    const long nMLP = (long)B_ * S_ * 4 * D_;      // 16777216

    // 1. adaLN projection
    ada_kernel<<<768, 256>>>(c, ada_w, ada_b, ada);
    // 2. LN1 + modulate (sh_msa@0, sc_msa@1024)
    ln_mod_kernel<<<B_ * S_, 256>>>(x, norm1_w, ada, 0, D_, h);
    // 3. QKV GEMM: [4096,1024] @ [3072,1024]^T
    gemm_nt<<<dim3(24, 32, 1), 256>>>(h, w_qkv, qkv, B_ * S_, 3 * D_, D_,
                                      D_, D_, 3 * D_, 1.f, 0, 0, 0);
    // 4. repack to [B,H,S,HD]
    repack_qkv<<<(unsigned)((nQKV + 255) / 256), 256>>>(qkv, q, k, v);
    // 5. scores = Q K^T / 8, batched over B*H
    gemm_nt<<<dim3(16, 16, 32), 256>>>(q, k, sc, S_, S_, HD_,
                                       HD_, HD_, S_, 0.125f,
                                       (long)S_ * HD_, (long)S_ * HD_, (long)S_ * S_);
    // 6. softmax
    softmax_kernel<<<B_ * H_ * S_, 256>>>(sc);
    // 7. attn = P @ V, batched
    gemm_nn_pv<<<dim3(1, 16, 32), 256>>>(sc, v, attn, S_, S_, S_,
                                         (long)S_ * S_, (long)S_ * HD_, (long)S_ * HD_);
    // 8. unpack to [B,S,D]
    unpack_attn<<<(unsigned)((nBSD + 255) / 256), 256>>>(attn, attn2);
    // 9. out-proj GEMM
    gemm_nt<<<dim3(8, 32, 1), 256>>>(attn2, w_out, h, B_ * S_, D_, D_,
                                     D_, D_, D_, 1.f, 0, 0, 0);
    // 10. x1 = x + g_msa * proj
    resid1_kernel<<<(unsigned)((nBSD + 255) / 256), 256>>>(x, h, ada, x1);
    // 11. LN2 + modulate (sh_mlp@3072, sc_mlp@4096)
    ln_mod_kernel<<<B_ * S_, 256>>>(x1, norm2_w, ada, 3 * D_, 4 * D_, h);
    // 12. MLP1 GEMM: [4096,1024] @ [4096,1024]^T
    gemm_nt<<<dim3(32, 32, 1), 256>>>(h, mlp_w1, mlp, B_ * S_, 4 * D_, D_,
                                      D_, D_, 4 * D_, 1.f, 0, 0, 0);
    // 13. bias + gelu
    bias_gelu_kernel<<<(unsigned)((nMLP + 255) / 256), 256>>>(mlp, mlp_b1);
    // 14. MLP2 GEMM: [4096,4096] @ [1024,4096]^T
    gemm_nt<<<dim3(8, 32, 1), 256>>>(mlp, mlp_w2, t, B_ * S_, D_, 4 * D_,
                                     4 * D_, 4 * D_, D_, 1.f, 0, 0, 0);
    // 15. out = x1 + g_mlp * (t + b2)
    final_kernel<<<(unsigned)((nBSD + 255) / 256), 256>>>(x1, t, mlp_b2, ada, out);
}

// round 2
// speedup vs baseline: 1.9733x; 1.9733x over previous
#include <cuda_runtime.h>
#include <math.h>

#define B_ 2
#define S_ 2048
#define D_ 1024
#define H_ 16
#define HD_ 64

// ---------------- scratch ----------------
__device__ float g_ada[B_ * 6 * D_];
__device__ float g_h[(size_t)B_ * S_ * D_];
__device__ float g_qkv[(size_t)B_ * S_ * 3 * D_];
__device__ float g_q[(size_t)B_ * H_ * S_ * HD_];
__device__ float g_k[(size_t)B_ * H_ * S_ * HD_];
__device__ float g_vt[(size_t)B_ * H_ * HD_ * S_];        // V transposed [B,H,HD,S]
__device__ float g_scores[(size_t)B_ * H_ * S_ * S_];
__device__ float g_attn[(size_t)B_ * H_ * S_ * HD_];
__device__ float g_attn2[(size_t)B_ * S_ * D_];
__device__ float g_x1[(size_t)B_ * S_ * D_];
__device__ float g_mlp[(size_t)B_ * S_ * 4 * D_];
__device__ float g_t[(size_t)B_ * S_ * D_];

__device__ __forceinline__ unsigned f2tf(float f) {
    unsigned u;
    asm("cvt.rna.tf32.f32 %0, %1;" : "=r"(u) : "f"(f));
    return u;
}

// ---------------- TF32 tensor-core NT GEMM ----------------
// C[M,N] = alpha * A[M,K] @ B[N,K]^T   (fp32 in/out, tf32 mma, fp32 accum)
// M%128==0, K%16==0, N arbitrary >0 (predicated), batched over blockIdx.z.
__global__ void __launch_bounds__(256) gemm_nt_tf32(
    const float* __restrict__ A, const float* __restrict__ B, float* __restrict__ C,
    int M, int N, int K, int lda, int ldb, int ldc, float alpha,
    long sA, long sB, long sC)
{
    A += (long)blockIdx.z * sA;
    B += (long)blockIdx.z * sB;
    C += (long)blockIdx.z * sC;

    __shared__ unsigned As[2][128][20];
    __shared__ unsigned Bs[2][128][20];

    const int tid   = threadIdx.x;
    const int lane  = tid & 31;
    const int warp  = tid >> 5;
    const int warpM = warp & 1;        // 2 warps along M
    const int warpN = warp >> 1;       // 4 warps along N
    const int grp   = lane >> 2;
    const int tig   = lane & 3;

    const int rowBase = blockIdx.y * 128;
    const int colBase = blockIdx.x * 128;

    // global loader mapping: each thread loads 2 float4 per operand per chunk
    const int rowA = tid >> 2;          // 0..63
    const int quad = tid & 3;           // which float4 along k
    const bool bv0 = (colBase + rowA)      < N;
    const bool bv1 = (colBase + rowA + 64) < N;

    float acc[4][4][4];
#pragma unroll
    for (int i = 0; i < 4; i++)
#pragma unroll
        for (int j = 0; j < 4; j++)
#pragma unroll
            for (int t = 0; t < 4; t++) acc[i][j][t] = 0.f;

    const int nCh = K >> 4;
    float4 ra0, ra1, rb0, rb1;
    const float4 z4 = make_float4(0.f, 0.f, 0.f, 0.f);

    // --- prologue: load chunk 0 ---
    {
        int k0 = 0;
        ra0 = *reinterpret_cast<const float4*>(&A[(rowBase + rowA) * lda + k0 + quad * 4]);
        ra1 = *reinterpret_cast<const float4*>(&A[(rowBase + rowA + 64) * lda + k0 + quad * 4]);
        rb0 = bv0 ? *reinterpret_cast<const float4*>(&B[(colBase + rowA) * ldb + k0 + quad * 4]) : z4;
        rb1 = bv1 ? *reinterpret_cast<const float4*>(&B[(colBase + rowA + 64) * ldb + k0 + quad * 4]) : z4;
    }
    {
        uint4 p;
        p.x = f2tf(ra0.x); p.y = f2tf(ra0.y); p.z = f2tf(ra0.z); p.w = f2tf(ra0.w);
        *reinterpret_cast<uint4*>(&As[0][rowA][quad * 4]) = p;
        p.x = f2tf(ra1.x); p.y = f2tf(ra1.y); p.z = f2tf(ra1.z); p.w = f2tf(ra1.w);
        *reinterpret_cast<uint4*>(&As[0][rowA + 64][quad * 4]) = p;
        p.x = f2tf(rb0.x); p.y = f2tf(rb0.y); p.z = f2tf(rb0.z); p.w = f2tf(rb0.w);
        *reinterpret_cast<uint4*>(&Bs[0][rowA][quad * 4]) = p;
        p.x = f2tf(rb1.x); p.y = f2tf(rb1.y); p.z = f2tf(rb1.z); p.w = f2tf(rb1.w);
        *reinterpret_cast<uint4*>(&Bs[0][rowA + 64][quad * 4]) = p;
    }
    __syncthreads();

    int buf = 0;
    for (int c = 0; c < nCh; c++) {
        const bool hasNext = (c + 1) < nCh;
        if (hasNext) {
            int k0 = (c + 1) << 4;
            ra0 = *reinterpret_cast<const float4*>(&A[(rowBase + rowA) * lda + k0 + quad * 4]);
            ra1 = *reinterpret_cast<const float4*>(&A[(rowBase + rowA + 64) * lda + k0 + quad * 4]);
            rb0 = bv0 ? *reinterpret_cast<const float4*>(&B[(colBase + rowA) * ldb + k0 + quad * 4]) : z4;
            rb1 = bv1 ? *reinterpret_cast<const float4*>(&B[(colBase + rowA + 64) * ldb + k0 + quad * 4]) : z4;
        }

        // --- compute chunk from smem[buf]: two k8 steps ---
#pragma unroll
        for (int kb = 0; kb < 2; kb++) {
            const int kk = kb * 8;
            unsigned af[4][4], bfr[4][2];
#pragma unroll
            for (int i = 0; i < 4; i++) {
                int r0 = warpM * 64 + i * 16 + grp;
                af[i][0] = As[buf][r0][kk + tig];
                af[i][1] = As[buf][r0 + 8][kk + tig];
                af[i][2] = As[buf][r0][kk + tig + 4];
                af[i][3] = As[buf][r0 + 8][kk + tig + 4];
            }
#pragma unroll
            for (int j = 0; j < 4; j++) {
                int c0 = warpN * 32 + j * 8 + grp;
                bfr[j][0] = Bs[buf][c0][kk + tig];
                bfr[j][1] = Bs[buf][c0][kk + tig + 4];
            }
#pragma unroll
            for (int i = 0; i < 4; i++)
#pragma unroll
                for (int j = 0; j < 4; j++) {
                    asm volatile(
                        "mma.sync.aligned.m16n8k8.row.col.f32.tf32.tf32.f32 "
                        "{%0,%1,%2,%3}, {%4,%5,%6,%7}, {%8,%9}, {%0,%1,%2,%3};"
                        : "+f"(acc[i][j][0]), "+f"(acc[i][j][1]),
                          "+f"(acc[i][j][2]), "+f"(acc[i][j][3])
                        : "r"(af[i][0]), "r"(af[i][1]), "r"(af[i][2]), "r"(af[i][3]),
                          "r"(bfr[j][0]), "r"(bfr[j][1]));
                }
        }

        if (hasNext) {
            int nb = buf ^ 1;
            uint4 p;
            p.x = f2tf(ra0.x); p.y = f2tf(ra0.y); p.z = f2tf(ra0.z); p.w = f2tf(ra0.w);
            *reinterpret_cast<uint4*>(&As[nb][rowA][quad * 4]) = p;
            p.x = f2tf(ra1.x); p.y = f2tf(ra1.y); p.z = f2tf(ra1.z); p.w = f2tf(ra1.w);
            *reinterpret_cast<uint4*>(&As[nb][rowA + 64][quad * 4]) = p;
            p.x = f2tf(rb0.x); p.y = f2tf(rb0.y); p.z = f2tf(rb0.z); p.w = f2tf(rb0.w);
            *reinterpret_cast<uint4*>(&Bs[nb][rowA][quad * 4]) = p;
            p.x = f2tf(rb1.x); p.y = f2tf(rb1.y); p.z = f2tf(rb1.z); p.w = f2tf(rb1.w);
            *reinterpret_cast<uint4*>(&Bs[nb][rowA + 64][quad * 4]) = p;
            __syncthreads();
        }
        buf ^= 1;
    }

    // --- epilogue ---
#pragma unroll
    for (int i = 0; i < 4; i++) {
#pragma unroll
        for (int j = 0; j < 4; j++) {
            int row = rowBase + warpM * 64 + i * 16 + grp;
            int col = colBase + warpN * 32 + j * 8 + tig * 2;
            if (col < N) {
                float2 v0 = make_float2(acc[i][j][0] * alpha, acc[i][j][1] * alpha);
                *reinterpret_cast<float2*>(&C[(long)row * ldc + col]) = v0;
                float2 v1 = make_float2(acc[i][j][2] * alpha, acc[i][j][3] * alpha);
                *reinterpret_cast<float2*>(&C[(long)(row + 8) * ldc + col]) = v1;
            }
        }
    }
}

// ---------------- adaLN ----------------
__global__ void __launch_bounds__(256) ada_kernel(
    const float* __restrict__ c, const float* __restrict__ w,
    const float* __restrict__ bias, float* __restrict__ out)
{
    int warp = (blockIdx.x * blockDim.x + threadIdx.x) >> 5;
    int lane = threadIdx.x & 31;
    if (warp >= 6 * D_) return;
    const float* wr = w + (long)warp * D_;
    float s0 = 0.f, s1 = 0.f;
    for (int d = lane; d < D_; d += 32) {
        float wv = wr[d];
        s0 += c[d] * wv;
        s1 += c[D_ + d] * wv;
    }
#pragma unroll
    for (int o = 16; o > 0; o >>= 1) {
        s0 += __shfl_down_sync(0xffffffffu, s0, o);
        s1 += __shfl_down_sync(0xffffffffu, s1, o);
    }
    if (lane == 0) {
        out[warp] = s0 + bias[warp];
        out[6 * D_ + warp] = s1 + bias[warp];
    }
}

// ---------------- LayerNorm + modulate ----------------
__global__ void __launch_bounds__(256) ln_mod_kernel(
    const float* __restrict__ x, const float* __restrict__ w,
    const float* __restrict__ ada, int shOff, int scOff, float* __restrict__ h)
{
    int r = blockIdx.x;
    int b = r >> 11;
    const float* xr = x + (long)r * D_;
    int tid = threadIdx.x;
    float s = 0.f, ss = 0.f;
    float vals[4];
#pragma unroll
    for (int i = 0; i < 4; i++) {
        float v = xr[tid + i * 256];
        vals[i] = v; s += v; ss += v * v;
    }
    __shared__ float rs[256], rss[256];
    rs[tid] = s; rss[tid] = ss;
    __syncthreads();
    for (int st = 128; st > 0; st >>= 1) {
        if (tid < st) { rs[tid] += rs[tid + st]; rss[tid] += rss[tid + st]; }
        __syncthreads();
    }
    float mean = rs[0] * (1.f / D_);
    float var = rss[0] * (1.f / D_) - mean * mean;
    float inv = rsqrtf(var + 1e-5f);
    const float* sh = ada + b * 6 * D_ + shOff;
    const float* sc = ada + b * 6 * D_ + scOff;
#pragma unroll
    for (int i = 0; i < 4; i++) {
        int d = tid + i * 256;
        h[(long)r * D_ + d] = (vals[i] - mean) * inv * w[d] * (1.f + sc[d]) + sh[d];
    }
}

// ---------------- repack qkv [B,S,3,H,HD] -> q/k [B,H,S,HD], v -> vt [B,H,HD,S] ----------------
__global__ void repack_qkv(const float* __restrict__ qkv,
                           float* __restrict__ q, float* __restrict__ k, float* __restrict__ vt)
{
    long idx = (long)blockIdx.x * 256 + threadIdx.x;
    if (idx >= (long)B_ * H_ * S_ * HD_) return;
    long t = idx;
    int hd = t & 63; t >>= 6;
    int s = t & 2047; t >>= 11;
    int h = t & 15; t >>= 4;
    int b = (int)t;
    long src = ((long)(b * S_ + s) * 3) * D_ + h * 64 + hd;
    q[idx] = qkv[src];
    k[idx] = qkv[src + D_];
    vt[(((long)b * H_ + h) * HD_ + hd) * S_ + s] = qkv[src + 2 * D_];
}

// ---------------- unpack attn [B,H,S,HD] -> [B,S,D] ----------------
__global__ void unpack_attn(const float* __restrict__ a, float* __restrict__ o)
{
    long idx = (long)blockIdx.x * 256 + threadIdx.x;
    if (idx >= (long)B_ * S_ * D_) return;
    long t = idx;
    int hd = t & 63; t >>= 6;
    int h = t & 15; t >>= 4;
    int s = t & 2047; t >>= 11;
    int b = (int)t;
    long src = ((long)(b * H_ + h) * S_ + s) * 64 + hd;
    o[idx] = a[src];
}

// ---------------- row softmax over 2048 ----------------
__global__ void __launch_bounds__(256) softmax_kernel(float* __restrict__ scp)
{
    long row = blockIdx.x;
    float* p = scp + row * (long)S_;
    __shared__ float buf[S_];
    __shared__ float red[256];
    int tid = threadIdx.x;
    float m = -INFINITY;
    for (int i = tid; i < S_; i += 256) {
        float v = p[i]; buf[i] = v; m = fmaxf(m, v);
    }
    red[tid] = m;
    __syncthreads();
    for (int s = 128; s > 0; s >>= 1) {
        if (tid < s) red[tid] = fmaxf(red[tid], red[tid + s]);
        __syncthreads();
    }
    m = red[0];
    __syncthreads();
    float sum = 0.f;
    for (int i = tid; i < S_; i += 256) {
        float e = __expf(buf[i] - m);
        buf[i] = e; sum += e;
    }
    red[tid] = sum;
    __syncthreads();
    for (int s = 128; s > 0; s >>= 1) {
        if (tid < s) red[tid] += red[tid + s];
        __syncthreads();
    }
    float inv = 1.f / red[0];
    for (int i = tid; i < S_; i += 256) p[i] = buf[i] * inv;
}

// ---------------- residual 1 ----------------
__global__ void resid1_kernel(const float* __restrict__ x, const float* __restrict__ proj,
                              const float* __restrict__ ada, float* __restrict__ x1)
{
    long idx = (long)blockIdx.x * 256 + threadIdx.x;
    if (idx >= (long)B_ * S_ * D_) return;
    int d = (int)(idx & (D_ - 1));
    int b = (int)(idx >> 21);
    x1[idx] = x[idx] + ada[b * 6 * D_ + 2 * D_ + d] * proj[idx];
}

// ---------------- bias + gelu ----------------
__global__ void bias_gelu_kernel(float* __restrict__ m, const float* __restrict__ b1)
{
    long idx = (long)blockIdx.x * 256 + threadIdx.x;
    if (idx >= (long)B_ * S_ * 4 * D_) return;
    int col = (int)(idx & (4 * D_ - 1));
    float v = m[idx] + b1[col];
    float u = 0.7978845608028654f * (v + 0.044715f * v * v * v);
    m[idx] = 0.5f * v * (1.f + tanhf(u));
}

// ---------------- final ----------------
__global__ void final_kernel(const float* __restrict__ x1, const float* __restrict__ t,
                             const float* __restrict__ b2, const float* __restrict__ ada,
                             float* __restrict__ out)
{
    long idx = (long)blockIdx.x * 256 + threadIdx.x;
    if (idx >= (long)B_ * S_ * D_) return;
    int d = (int)(idx & (D_ - 1));
    int b = (int)(idx >> 21);
    out[idx] = x1[idx] + ada[b * 6 * D_ + 5 * D_ + d] * (t[idx] + b2[d]);
}

// ---------------- launch ----------------
extern "C" void kernel_launch(void* const* d_in, const int* in_sizes, int n_in,
                              void* d_out, int out_size)
{
    (void)in_sizes; (void)n_in; (void)out_size;
    const float* x       = (const float*)d_in[0];
    const float* c       = (const float*)d_in[3];
    const float* norm1_w = (const float*)d_in[4];
    const float* w_qkv   = (const float*)d_in[5];
    const float* w_out   = (const float*)d_in[6];
    const float* norm2_w = (const float*)d_in[7];
    const float* mlp_w1  = (const float*)d_in[8];
    const float* mlp_b1  = (const float*)d_in[9];
    const float* mlp_w2  = (const float*)d_in[10];
    const float* mlp_b2  = (const float*)d_in[11];
    const float* ada_w   = (const float*)d_in[12];
    const float* ada_b   = (const float*)d_in[13];
    float* out = (float*)d_out;

    float *ada, *h, *qkv, *q, *k, *vt, *sc, *attn, *attn2, *x1, *mlp, *t;
    cudaGetSymbolAddress((void**)&ada,   g_ada);
    cudaGetSymbolAddress((void**)&h,     g_h);
    cudaGetSymbolAddress((void**)&qkv,   g_qkv);
    cudaGetSymbolAddress((void**)&q,     g_q);
    cudaGetSymbolAddress((void**)&k,     g_k);
    cudaGetSymbolAddress((void**)&vt,    g_vt);
    cudaGetSymbolAddress((void**)&sc,    g_scores);
    cudaGetSymbolAddress((void**)&attn,  g_attn);
    cudaGetSymbolAddress((void**)&attn2, g_attn2);
    cudaGetSymbolAddress((void**)&x1,    g_x1);
    cudaGetSymbolAddress((void**)&mlp,   g_mlp);
    cudaGetSymbolAddress((void**)&t,     g_t);

    const long nBSD = (long)B_ * S_ * D_;
    const long nQKV = (long)B_ * H_ * S_ * HD_;
    const long nMLP = (long)B_ * S_ * 4 * D_;

    // 1. adaLN projection
    ada_kernel<<<768, 256>>>(c, ada_w, ada_b, ada);
    // 2. LN1 + modulate
    ln_mod_kernel<<<B_ * S_, 256>>>(x, norm1_w, ada, 0, D_, h);
    // 3. QKV GEMM [4096,1024] @ [3072,1024]^T
    gemm_nt_tf32<<<dim3(24, 32, 1), 256>>>(h, w_qkv, qkv, B_ * S_, 3 * D_, D_,
                                           D_, D_, 3 * D_, 1.f, 0, 0, 0);
    // 4. repack (v transposed)
    repack_qkv<<<(unsigned)((nQKV + 255) / 256), 256>>>(qkv, q, k, vt);
    // 5. scores = Q K^T / 8
    gemm_nt_tf32<<<dim3(16, 16, 32), 256>>>(q, k, sc, S_, S_, HD_,
                                            HD_, HD_, S_, 0.125f,
                                            (long)S_ * HD_, (long)S_ * HD_, (long)S_ * S_);
    // 6. softmax
    softmax_kernel<<<B_ * H_ * S_, 256>>>(sc);
    // 7. attn = P @ Vt^T  (M=2048, N=64, K=2048)
    gemm_nt_tf32<<<dim3(1, 16, 32), 256>>>(sc, vt, attn, S_, HD_, S_,
                                           S_, S_, HD_, 1.f,
                                           (long)S_ * S_, (long)S_ * HD_, (long)S_ * HD_);
    // 8. unpack
    unpack_attn<<<(unsigned)((nBSD + 255) / 256), 256>>>(attn, attn2);
    // 9. out-proj
    gemm_nt_tf32<<<dim3(8, 32, 1), 256>>>(attn2, w_out, h, B_ * S_, D_, D_,
                                          D_, D_, D_, 1.f, 0, 0, 0);
    // 10. residual 1
    resid1_kernel<<<(unsigned)((nBSD + 255) / 256), 256>>>(x, h, ada, x1);
    // 11. LN2 + modulate
    ln_mod_kernel<<<B_ * S_, 256>>>(x1, norm2_w, ada, 3 * D_, 4 * D_, h);
    // 12. MLP1
    gemm_nt_tf32<<<dim3(32, 32, 1), 256>>>(h, mlp_w1, mlp, B_ * S_, 4 * D_, D_,
                                           D_, D_, 4 * D_, 1.f, 0, 0, 0);
    // 13. bias + gelu
    bias_gelu_kernel<<<(unsigned)((nMLP + 255) / 256), 256>>>(mlp, mlp_b1);
    // 14. MLP2
    gemm_nt_tf32<<<dim3(8, 32, 1), 256>>>(mlp, mlp_w2, t, B_ * S_, D_, 4 * D_,
                                          4 * D_, 4 * D_, D_, 1.f, 0, 0, 0);
    // 15. final
    final_kernel<<<(unsigned)((nBSD + 255) / 256), 256>>>(x1, t, mlp_b2, ada, out);
}

// round 3
// speedup vs baseline: 2.9604x; 1.5002x over previous
#include <cuda_runtime.h>
#include <math.h>

#define B_ 2
#define S_ 2048
#define D_ 1024
#define H_ 16
#define HD_ 64

// ---------------- scratch ----------------
__device__ float g_ada[B_ * 6 * D_];
__device__ float g_h[(size_t)B_ * S_ * D_];
__device__ float g_qkv[(size_t)B_ * S_ * 3 * D_];
__device__ float g_attn2[(size_t)B_ * S_ * D_];
__device__ float g_x1[(size_t)B_ * S_ * D_];
__device__ float g_mlp[(size_t)B_ * S_ * 4 * D_];

__device__ __forceinline__ unsigned f2tf(float f) {
    unsigned u;
    asm("cvt.rna.tf32.f32 %0, %1;" : "=r"(u) : "f"(f));
    return u;
}

__device__ __forceinline__ float gelu_tanh(float v) {
    float u = 0.7978845608028654f * (v + 0.044715f * v * v * v);
    return 0.5f * v * (1.f + tanhf(u));
}

// ============================================================================
// Fused flash attention (tf32 mma, online softmax).
// qkv: [B, S, 3, H, HD] fp32. out: [B, S, H*HD] fp32.
// Block: 128 query rows of one (b,h). 256 threads = 8 warps, 16 q-rows/warp.
// Key tiles of 64. Q pre-scaled by 1/8.
// ============================================================================
#define FA_SMEM 105472

__global__ void __launch_bounds__(256) flash_attn(
    const float* __restrict__ qkv, float* __restrict__ out)
{
    extern __shared__ unsigned sm[];
    unsigned* Qs  = sm;                    // [128][68]
    unsigned* Ks  = sm + 128 * 68;         // [64][68]   rows=key, cols=dim
    unsigned* Vs  = Ks + 64 * 68;          // [64][72]   rows=key, cols=hd
    unsigned* Psw = Vs + 64 * 72;          // 8 x [16][68]

    const int tid  = threadIdx.x;
    const int lane = tid & 31;
    const int warp = tid >> 5;
    const int grp  = lane >> 2;            // 0..7
    const int tig  = lane & 3;             // 0..3
    const int b    = blockIdx.y >> 4;
    const int h    = blockIdx.y & 15;
    const int qBase = blockIdx.x * 128;

    // ---- load Q tile (scaled by 1/8), convert to tf32 ----
#pragma unroll
    for (int i = 0; i < 8; i++) {
        int idx = tid + i * 256;           // 0..2047
        int r   = idx >> 4;                // 0..127
        int qd  = idx & 15;                // float4 index
        const float4 v = *reinterpret_cast<const float4*>(
            &qkv[((long)(b * S_ + qBase + r)) * 3072 + h * 64 + qd * 4]);
        unsigned* dst = &Qs[r * 68 + qd * 4];
        dst[0] = f2tf(v.x * 0.125f); dst[1] = f2tf(v.y * 0.125f);
        dst[2] = f2tf(v.z * 0.125f); dst[3] = f2tf(v.w * 0.125f);
    }

    unsigned* Ps = Psw + warp * 16 * 68;
    const unsigned* Qw = Qs + warp * 16 * 68;

    float m0 = -INFINITY, m1 = -INFINITY, l0 = 0.f, l1 = 0.f;
    float o[8][4];
#pragma unroll
    for (int j = 0; j < 8; j++)
#pragma unroll
        for (int t = 0; t < 4; t++) o[j][t] = 0.f;

    for (int kt = 0; kt < S_; kt += 64) {
        __syncthreads();
        // ---- load K,V tiles ----
#pragma unroll
        for (int i = 0; i < 4; i++) {
            int idx = tid + i * 256;       // 0..1023
            int r   = idx >> 4;            // 0..63
            int qd  = idx & 15;
            long rowoff = ((long)(b * S_ + kt + r)) * 3072 + h * 64 + qd * 4;
            const float4 kv = *reinterpret_cast<const float4*>(&qkv[rowoff + 1024]);
            unsigned* dk = &Ks[r * 68 + qd * 4];
            dk[0] = f2tf(kv.x); dk[1] = f2tf(kv.y); dk[2] = f2tf(kv.z); dk[3] = f2tf(kv.w);
            const float4 vv = *reinterpret_cast<const float4*>(&qkv[rowoff + 2048]);
            unsigned* dv = &Vs[r * 72 + qd * 4];
            dv[0] = f2tf(vv.x); dv[1] = f2tf(vv.y); dv[2] = f2tf(vv.z); dv[3] = f2tf(vv.w);
        }
        __syncthreads();

        // ---- scores = Q @ K^T (16 rows x 64 cols per warp) ----
        float s[8][4];
#pragma unroll
        for (int j = 0; j < 8; j++)
#pragma unroll
            for (int t = 0; t < 4; t++) s[j][t] = 0.f;

#pragma unroll
        for (int kk = 0; kk < 64; kk += 8) {
            unsigned a0 = Qw[grp * 68 + kk + tig];
            unsigned a1 = Qw[(grp + 8) * 68 + kk + tig];
            unsigned a2 = Qw[grp * 68 + kk + tig + 4];
            unsigned a3 = Qw[(grp + 8) * 68 + kk + tig + 4];
#pragma unroll
            for (int j = 0; j < 8; j++) {
                unsigned b0 = Ks[(j * 8 + grp) * 68 + kk + tig];
                unsigned b1 = Ks[(j * 8 + grp) * 68 + kk + tig + 4];
                asm volatile(
                    "mma.sync.aligned.m16n8k8.row.col.f32.tf32.tf32.f32 "
                    "{%0,%1,%2,%3}, {%4,%5,%6,%7}, {%8,%9}, {%0,%1,%2,%3};"
                    : "+f"(s[j][0]), "+f"(s[j][1]), "+f"(s[j][2]), "+f"(s[j][3])
                    : "r"(a0), "r"(a1), "r"(a2), "r"(a3), "r"(b0), "r"(b1));
            }
        }

        // ---- online softmax ----
        float mx0 = -INFINITY, mx1 = -INFINITY;
#pragma unroll
        for (int j = 0; j < 8; j++) {
            mx0 = fmaxf(mx0, fmaxf(s[j][0], s[j][1]));
            mx1 = fmaxf(mx1, fmaxf(s[j][2], s[j][3]));
        }
        mx0 = fmaxf(mx0, __shfl_xor_sync(0xffffffffu, mx0, 1));
        mx0 = fmaxf(mx0, __shfl_xor_sync(0xffffffffu, mx0, 2));
        mx1 = fmaxf(mx1, __shfl_xor_sync(0xffffffffu, mx1, 1));
        mx1 = fmaxf(mx1, __shfl_xor_sync(0xffffffffu, mx1, 2));
        float mn0 = fmaxf(m0, mx0), mn1 = fmaxf(m1, mx1);
        float sc0 = __expf(m0 - mn0), sc1 = __expf(m1 - mn1);

        float sum0 = 0.f, sum1 = 0.f;
#pragma unroll
        for (int j = 0; j < 8; j++) {
            float p0 = __expf(s[j][0] - mn0);
            float p1 = __expf(s[j][1] - mn0);
            float p2 = __expf(s[j][2] - mn1);
            float p3 = __expf(s[j][3] - mn1);
            sum0 += p0 + p1; sum1 += p2 + p3;
            Ps[grp * 68 + j * 8 + tig * 2]            = f2tf(p0);
            Ps[grp * 68 + j * 8 + tig * 2 + 1]        = f2tf(p1);
            Ps[(grp + 8) * 68 + j * 8 + tig * 2]      = f2tf(p2);
            Ps[(grp + 8) * 68 + j * 8 + tig * 2 + 1]  = f2tf(p3);
        }
        sum0 += __shfl_xor_sync(0xffffffffu, sum0, 1);
        sum0 += __shfl_xor_sync(0xffffffffu, sum0, 2);
        sum1 += __shfl_xor_sync(0xffffffffu, sum1, 1);
        sum1 += __shfl_xor_sync(0xffffffffu, sum1, 2);
        l0 = l0 * sc0 + sum0;
        l1 = l1 * sc1 + sum1;
        m0 = mn0; m1 = mn1;

#pragma unroll
        for (int j = 0; j < 8; j++) {
            o[j][0] *= sc0; o[j][1] *= sc0;
            o[j][2] *= sc1; o[j][3] *= sc1;
        }
        __syncwarp();

        // ---- O += P @ V ----
#pragma unroll
        for (int kk = 0; kk < 64; kk += 8) {
            unsigned a0 = Ps[grp * 68 + kk + tig];
            unsigned a1 = Ps[(grp + 8) * 68 + kk + tig];
            unsigned a2 = Ps[grp * 68 + kk + tig + 4];
            unsigned a3 = Ps[(grp + 8) * 68 + kk + tig + 4];
#pragma unroll
            for (int j = 0; j < 8; j++) {
                unsigned b0 = Vs[(kk + tig) * 72 + j * 8 + grp];
                unsigned b1 = Vs[(kk + tig + 4) * 72 + j * 8 + grp];
                asm volatile(
                    "mma.sync.aligned.m16n8k8.row.col.f32.tf32.tf32.f32 "
                    "{%0,%1,%2,%3}, {%4,%5,%6,%7}, {%8,%9}, {%0,%1,%2,%3};"
                    : "+f"(o[j][0]), "+f"(o[j][1]), "+f"(o[j][2]), "+f"(o[j][3])
                    : "r"(a0), "r"(a1), "r"(a2), "r"(a3), "r"(b0), "r"(b1));
            }
        }
        __syncwarp();
    }

    // ---- normalize + store ----
    float inv0 = 1.f / l0, inv1 = 1.f / l1;
    int row0 = qBase + warp * 16 + grp;
#pragma unroll
    for (int j = 0; j < 8; j++) {
        int col = h * 64 + j * 8 + tig * 2;
        float2 v0 = make_float2(o[j][0] * inv0, o[j][1] * inv0);
        *reinterpret_cast<float2*>(&out[((long)(b * S_ + row0)) * D_ + col]) = v0;
        float2 v1 = make_float2(o[j][2] * inv1, o[j][3] * inv1);
        *reinterpret_cast<float2*>(&out[((long)(b * S_ + row0 + 8)) * D_ + col]) = v1;
    }
}

// ============================================================================
// TF32 tensor-core NT GEMM with fused epilogues.
// C[M,N] = epi(alpha * A[M,K] @ B[N,K]^T)
// mode 0: plain   mode 1: gelu(v + evec[col])
// mode 2: EX[row,col] + ada[b,adaOff+col] * v
// mode 3: EX[row,col] + ada[b,adaOff+col] * (v + evec[col])
// (modes 2/3 assume 2048 rows per batch)
// ============================================================================
__global__ void __launch_bounds__(256) gemm_nt_tf32(
    const float* __restrict__ A, const float* __restrict__ B, float* __restrict__ C,
    int M, int N, int K, int lda, int ldb, int ldc, float alpha,
    int mode, const float* __restrict__ EX, const float* __restrict__ evec,
    const float* __restrict__ ada, int adaOff)
{
    __shared__ unsigned As[2][128][20];
    __shared__ unsigned Bs[2][128][20];

    const int tid   = threadIdx.x;
    const int lane  = tid & 31;
    const int warp  = tid >> 5;
    const int warpM = warp & 1;
    const int warpN = warp >> 1;
    const int grp   = lane >> 2;
    const int tig   = lane & 3;

    const int rowBase = blockIdx.y * 128;
    const int colBase = blockIdx.x * 128;

    const int rowA = tid >> 2;
    const int quad = tid & 3;
    const bool bv0 = (colBase + rowA)      < N;
    const bool bv1 = (colBase + rowA + 64) < N;

    float acc[4][4][4];
#pragma unroll
    for (int i = 0; i < 4; i++)
#pragma unroll
        for (int j = 0; j < 4; j++)
#pragma unroll
            for (int t = 0; t < 4; t++) acc[i][j][t] = 0.f;

    const int nCh = K >> 4;
    float4 ra0, ra1, rb0, rb1;
    const float4 z4 = make_float4(0.f, 0.f, 0.f, 0.f);

    {
        ra0 = *reinterpret_cast<const float4*>(&A[(long)(rowBase + rowA) * lda + quad * 4]);
        ra1 = *reinterpret_cast<const float4*>(&A[(long)(rowBase + rowA + 64) * lda + quad * 4]);
        rb0 = bv0 ? *reinterpret_cast<const float4*>(&B[(long)(colBase + rowA) * ldb + quad * 4]) : z4;
        rb1 = bv1 ? *reinterpret_cast<const float4*>(&B[(long)(colBase + rowA + 64) * ldb + quad * 4]) : z4;
    }
    {
        uint4 p;
        p.x = f2tf(ra0.x); p.y = f2tf(ra0.y); p.z = f2tf(ra0.z); p.w = f2tf(ra0.w);
        *reinterpret_cast<uint4*>(&As[0][rowA][quad * 4]) = p;
        p.x = f2tf(ra1.x); p.y = f2tf(ra1.y); p.z = f2tf(ra1.z); p.w = f2tf(ra1.w);
        *reinterpret_cast<uint4*>(&As[0][rowA + 64][quad * 4]) = p;
        p.x = f2tf(rb0.x); p.y = f2tf(rb0.y); p.z = f2tf(rb0.z); p.w = f2tf(rb0.w);
        *reinterpret_cast<uint4*>(&Bs[0][rowA][quad * 4]) = p;
        p.x = f2tf(rb1.x); p.y = f2tf(rb1.y); p.z = f2tf(rb1.z); p.w = f2tf(rb1.w);
        *reinterpret_cast<uint4*>(&Bs[0][rowA + 64][quad * 4]) = p;
    }
    __syncthreads();

    int buf = 0;
    for (int c = 0; c < nCh; c++) {
        const bool hasNext = (c + 1) < nCh;
        if (hasNext) {
            int k0 = (c + 1) << 4;
            ra0 = *reinterpret_cast<const float4*>(&A[(long)(rowBase + rowA) * lda + k0 + quad * 4]);
            ra1 = *reinterpret_cast<const float4*>(&A[(long)(rowBase + rowA + 64) * lda + k0 + quad * 4]);
            rb0 = bv0 ? *reinterpret_cast<const float4*>(&B[(long)(colBase + rowA) * ldb + k0 + quad * 4]) : z4;
            rb1 = bv1 ? *reinterpret_cast<const float4*>(&B[(long)(colBase + rowA + 64) * ldb + k0 + quad * 4]) : z4;
        }

#pragma unroll
        for (int kb = 0; kb < 2; kb++) {
            const int kk = kb * 8;
            unsigned af[4][4], bfr[4][2];
#pragma unroll
            for (int i = 0; i < 4; i++) {
                int r0 = warpM * 64 + i * 16 + grp;
                af[i][0] = As[buf][r0][kk + tig];
                af[i][1] = As[buf][r0 + 8][kk + tig];
                af[i][2] = As[buf][r0][kk + tig + 4];
                af[i][3] = As[buf][r0 + 8][kk + tig + 4];
            }
#pragma unroll
            for (int j = 0; j < 4; j++) {
                int c0 = warpN * 32 + j * 8 + grp;
                bfr[j][0] = Bs[buf][c0][kk + tig];
                bfr[j][1] = Bs[buf][c0][kk + tig + 4];
            }
#pragma unroll
            for (int i = 0; i < 4; i++)
#pragma unroll
                for (int j = 0; j < 4; j++) {
                    asm volatile(
                        "mma.sync.aligned.m16n8k8.row.col.f32.tf32.tf32.f32 "
                        "{%0,%1,%2,%3}, {%4,%5,%6,%7}, {%8,%9}, {%0,%1,%2,%3};"
                        : "+f"(acc[i][j][0]), "+f"(acc[i][j][1]),
                          "+f"(acc[i][j][2]), "+f"(acc[i][j][3])
                        : "r"(af[i][0]), "r"(af[i][1]), "r"(af[i][2]), "r"(af[i][3]),
                          "r"(bfr[j][0]), "r"(bfr[j][1]));
                }
        }

        if (hasNext) {
            int nb = buf ^ 1;
            uint4 p;
            p.x = f2tf(ra0.x); p.y = f2tf(ra0.y); p.z = f2tf(ra0.z); p.w = f2tf(ra0.w);
            *reinterpret_cast<uint4*>(&As[nb][rowA][quad * 4]) = p;
            p.x = f2tf(ra1.x); p.y = f2tf(ra1.y); p.z = f2tf(ra1.z); p.w = f2tf(ra1.w);
            *reinterpret_cast<uint4*>(&As[nb][rowA + 64][quad * 4]) = p;
            p.x = f2tf(rb0.x); p.y = f2tf(rb0.y); p.z = f2tf(rb0.z); p.w = f2tf(rb0.w);
            *reinterpret_cast<uint4*>(&Bs[nb][rowA][quad * 4]) = p;
            p.x = f2tf(rb1.x); p.y = f2tf(rb1.y); p.z = f2tf(rb1.z); p.w = f2tf(rb1.w);
            *reinterpret_cast<uint4*>(&Bs[nb][rowA + 64][quad * 4]) = p;
            __syncthreads();
        }
        buf ^= 1;
    }

#pragma unroll
    for (int i = 0; i < 4; i++) {
#pragma unroll
        for (int j = 0; j < 4; j++) {
            long row = rowBase + warpM * 64 + i * 16 + grp;
            int col = colBase + warpN * 32 + j * 8 + tig * 2;
            if (col < N) {
#pragma unroll
                for (int half = 0; half < 2; half++) {
                    long r = row + half * 8;
                    float v0 = acc[i][j][half * 2] * alpha;
                    float v1 = acc[i][j][half * 2 + 1] * alpha;
                    if (mode == 1) {
                        v0 = gelu_tanh(v0 + evec[col]);
                        v1 = gelu_tanh(v1 + evec[col + 1]);
                    } else if (mode == 2) {
                        int bb = (int)(r >> 11);
                        v0 = EX[r * ldc + col] + ada[bb * 6 * D_ + adaOff + col] * v0;
                        v1 = EX[r * ldc + col + 1] + ada[bb * 6 * D_ + adaOff + col + 1] * v1;
                    } else if (mode == 3) {
                        int bb = (int)(r >> 11);
                        v0 = EX[r * ldc + col] + ada[bb * 6 * D_ + adaOff + col] * (v0 + evec[col]);
                        v1 = EX[r * ldc + col + 1] + ada[bb * 6 * D_ + adaOff + col + 1] * (v1 + evec[col + 1]);
                    }
                    *reinterpret_cast<float2*>(&C[r * ldc + col]) = make_float2(v0, v1);
                }
            }
        }
    }
}

// ---------------- adaLN ----------------
__global__ void __launch_bounds__(256) ada_kernel(
    const float* __restrict__ c, const float* __restrict__ w,
    const float* __restrict__ bias, float* __restrict__ out)
{
    int warp = (blockIdx.x * blockDim.x + threadIdx.x) >> 5;
    int lane = threadIdx.x & 31;
    if (warp >= 6 * D_) return;
    const float* wr = w + (long)warp * D_;
    float s0 = 0.f, s1 = 0.f;
    for (int d = lane; d < D_; d += 32) {
        float wv = wr[d];
        s0 += c[d] * wv;
        s1 += c[D_ + d] * wv;
    }
#pragma unroll
    for (int o = 16; o > 0; o >>= 1) {
        s0 += __shfl_down_sync(0xffffffffu, s0, o);
        s1 += __shfl_down_sync(0xffffffffu, s1, o);
    }
    if (lane == 0) {
        out[warp] = s0 + bias[warp];
        out[6 * D_ + warp] = s1 + bias[warp];
    }
}

// ---------------- LayerNorm + modulate ----------------
__global__ void __launch_bounds__(256) ln_mod_kernel(
    const float* __restrict__ x, const float* __restrict__ w,
    const float* __restrict__ ada, int shOff, int scOff, float* __restrict__ h)
{
    int r = blockIdx.x;
    int b = r >> 11;
    const float* xr = x + (long)r * D_;
    int tid = threadIdx.x;
    float s = 0.f, ss = 0.f;
    float vals[4];
#pragma unroll
    for (int i = 0; i < 4; i++) {
        float v = xr[tid + i * 256];
        vals[i] = v; s += v; ss += v * v;
    }
    __shared__ float rs[256], rss[256];
    rs[tid] = s; rss[tid] = ss;
    __syncthreads();
    for (int st = 128; st > 0; st >>= 1) {
        if (tid < st) { rs[tid] += rs[tid + st]; rss[tid] += rss[tid + st]; }
        __syncthreads();
    }
    float mean = rs[0] * (1.f / D_);
    float var = rss[0] * (1.f / D_) - mean * mean;
    float inv = rsqrtf(var + 1e-5f);
    const float* sh = ada + b * 6 * D_ + shOff;
    const float* sc = ada + b * 6 * D_ + scOff;
#pragma unroll
    for (int i = 0; i < 4; i++) {
        int d = tid + i * 256;
        h[(long)r * D_ + d] = (vals[i] - mean) * inv * w[d] * (1.f + sc[d]) + sh[d];
    }
}

// ---------------- launch ----------------
extern "C" void kernel_launch(void* const* d_in, const int* in_sizes, int n_in,
                              void* d_out, int out_size)
{
    (void)in_sizes; (void)n_in; (void)out_size;
    const float* x       = (const float*)d_in[0];
    const float* c       = (const float*)d_in[3];
    const float* norm1_w = (const float*)d_in[4];
    const float* w_qkv   = (const float*)d_in[5];
    const float* w_out   = (const float*)d_in[6];
    const float* norm2_w = (const float*)d_in[7];
    const float* mlp_w1  = (const float*)d_in[8];
    const float* mlp_b1  = (const float*)d_in[9];
    const float* mlp_w2  = (const float*)d_in[10];
    const float* mlp_b2  = (const float*)d_in[11];
    const float* ada_w   = (const float*)d_in[12];
    const float* ada_b   = (const float*)d_in[13];
    float* out = (float*)d_out;

    float *ada, *h, *qkv, *attn2, *x1, *mlp;
    cudaGetSymbolAddress((void**)&ada,   g_ada);
    cudaGetSymbolAddress((void**)&h,     g_h);
    cudaGetSymbolAddress((void**)&qkv,   g_qkv);
    cudaGetSymbolAddress((void**)&attn2, g_attn2);
    cudaGetSymbolAddress((void**)&x1,    g_x1);
    cudaGetSymbolAddress((void**)&mlp,   g_mlp);

    static int fa_inited = 0;
    if (!fa_inited) {
        cudaFuncSetAttribute(flash_attn, cudaFuncAttributeMaxDynamicSharedMemorySize, FA_SMEM);
        fa_inited = 1;
    }

    // 1. adaLN projection
    ada_kernel<<<768, 256>>>(c, ada_w, ada_b, ada);
    // 2. LN1 + modulate
    ln_mod_kernel<<<B_ * S_, 256>>>(x, norm1_w, ada, 0, D_, h);
    // 3. QKV GEMM [4096,1024] @ [3072,1024]^T
    gemm_nt_tf32<<<dim3(24, 32), 256>>>(h, w_qkv, qkv, B_ * S_, 3 * D_, D_,
                                        D_, D_, 3 * D_, 1.f, 0, nullptr, nullptr, nullptr, 0);
    // 4. fused flash attention -> attn2 [B,S,D]
    flash_attn<<<dim3(S_ / 128, B_ * H_), 256, FA_SMEM>>>(qkv, attn2);
    // 5. out-proj + residual1 fused: x1 = x + g_msa * (attn2 @ w_out^T)
    gemm_nt_tf32<<<dim3(8, 32), 256>>>(attn2, w_out, x1, B_ * S_, D_, D_,
                                       D_, D_, D_, 1.f, 2, x, nullptr, ada, 2 * D_);
    // 6. LN2 + modulate
    ln_mod_kernel<<<B_ * S_, 256>>>(x1, norm2_w, ada, 3 * D_, 4 * D_, h);
    // 7. MLP1 + bias + gelu fused
    gemm_nt_tf32<<<dim3(32, 32), 256>>>(h, mlp_w1, mlp, B_ * S_, 4 * D_, D_,
                                        D_, D_, 4 * D_, 1.f, 1, nullptr, mlp_b1, nullptr, 0);
    // 8. MLP2 + final residual fused: out = x1 + g_mlp * (mlp @ w2^T + b2)
    gemm_nt_tf32<<<dim3(8, 32), 256>>>(mlp, mlp_w2, out, B_ * S_, D_, 4 * D_,
                                       4 * D_, 4 * D_, D_, 1.f, 3, x1, mlp_b2, ada, 5 * D_);
}

// round 4
// speedup vs baseline: 3.4464x; 1.1642x over previous
#include <cuda_runtime.h>
#include <math.h>

#define B_ 2
#define S_ 2048
#define D_ 1024
#define H_ 16
#define HD_ 64

// ---------------- scratch ----------------
__device__ float g_ada[B_ * 6 * D_];
__device__ float g_h[(size_t)B_ * S_ * D_];
__device__ float g_qkv[(size_t)B_ * S_ * 3 * D_];
__device__ float g_attn2[(size_t)B_ * S_ * D_];
__device__ float g_x1[(size_t)B_ * S_ * D_];
__device__ float g_mlp[(size_t)B_ * S_ * 4 * D_];

__device__ __forceinline__ unsigned f2tf(float f) {
    unsigned u;
    asm("cvt.rna.tf32.f32 %0, %1;" : "=r"(u) : "f"(f));
    return u;
}

__device__ __forceinline__ float gelu_tanh(float v) {
    float u = 0.7978845608028654f * (v + 0.044715f * v * v * v);
    return 0.5f * v * (1.f + tanhf(u));
}

__device__ __forceinline__ void cp16(void* s, const void* g) {
    unsigned sa = (unsigned)__cvta_generic_to_shared(s);
    asm volatile("cp.async.cg.shared.global [%0], [%1], 16;" :: "r"(sa), "l"(g));
}
#define CP_COMMIT() asm volatile("cp.async.commit_group;")
#define CP_WAIT(n)  asm volatile("cp.async.wait_group %0;" :: "n"(n))

// ============================================================================
// Fused flash attention (tf32 mma, online softmax, cp.async double-buffered KV)
// qkv: [B, S, 3, H, HD] fp32. out: [B, S, H*HD] fp32.
// Raw fp32 bits fed to tf32 mma (HW truncation); 1/8 scale applied post-mma.
// ============================================================================
#define FA_SMEM 141312

__global__ void __launch_bounds__(256) flash_attn(
    const float* __restrict__ qkv, float* __restrict__ out)
{
    extern __shared__ unsigned sm[];
    unsigned* Qs  = sm;                     // [128][68]
    unsigned* Ks  = sm + 8704;              // [2][64][68]
    unsigned* Vs  = sm + 17408;             // [2][64][72]
    unsigned* Psw = sm + 26624;             // 8 x [16][68]

    const int tid  = threadIdx.x;
    const int lane = tid & 31;
    const int warp = tid >> 5;
    const int grp  = lane >> 2;
    const int tig  = lane & 3;
    const int b    = blockIdx.y >> 4;
    const int h    = blockIdx.y & 15;
    const int qBase = blockIdx.x * 128;

    // ---- prologue: Q tile + KV tile 0 via cp.async ----
#pragma unroll
    for (int i = 0; i < 8; i++) {
        int idx = tid + i * 256;
        int r   = idx >> 4;
        int qd  = idx & 15;
        cp16(&Qs[r * 68 + qd * 4],
             &qkv[((long)(b * S_ + qBase + r)) * 3072 + h * 64 + qd * 4]);
    }
#pragma unroll
    for (int i = 0; i < 4; i++) {
        int idx = tid + i * 256;
        int r   = idx >> 4;
        int qd  = idx & 15;
        const float* base = &qkv[((long)(b * S_ + r)) * 3072 + h * 64 + qd * 4];
        cp16(&Ks[r * 68 + qd * 4], base + 1024);
        cp16(&Vs[r * 72 + qd * 4], base + 2048);
    }
    CP_COMMIT();

    unsigned* Ps = Psw + warp * 16 * 68;
    const unsigned* Qw = Qs + warp * 16 * 68;

    float m0 = -INFINITY, m1 = -INFINITY, l0 = 0.f, l1 = 0.f;
    float o[8][4];
#pragma unroll
    for (int j = 0; j < 8; j++)
#pragma unroll
        for (int t = 0; t < 4; t++) o[j][t] = 0.f;

    const int nT = S_ / 64;
    for (int t = 0; t < nT; t++) {
        CP_WAIT(0);
        __syncthreads();

        // prefetch next KV tile into other buffer
        if (t + 1 < nT) {
            unsigned* Kn = Ks + ((t + 1) & 1) * 4352;
            unsigned* Vn = Vs + ((t + 1) & 1) * 4608;
            int kt = (t + 1) * 64;
#pragma unroll
            for (int i = 0; i < 4; i++) {
                int idx = tid + i * 256;
                int r   = idx >> 4;
                int qd  = idx & 15;
                const float* base = &qkv[((long)(b * S_ + kt + r)) * 3072 + h * 64 + qd * 4];
                cp16(&Kn[r * 68 + qd * 4], base + 1024);
                cp16(&Vn[r * 72 + qd * 4], base + 2048);
            }
        }
        CP_COMMIT();

        const unsigned* Kc = Ks + (t & 1) * 4352;
        const unsigned* Vc = Vs + (t & 1) * 4608;

        // ---- scores = Q @ K^T ----
        float s[8][4];
#pragma unroll
        for (int j = 0; j < 8; j++)
#pragma unroll
            for (int tt = 0; tt < 4; tt++) s[j][tt] = 0.f;

#pragma unroll
        for (int kk = 0; kk < 64; kk += 8) {
            unsigned a0 = Qw[grp * 68 + kk + tig];
            unsigned a1 = Qw[(grp + 8) * 68 + kk + tig];
            unsigned a2 = Qw[grp * 68 + kk + tig + 4];
            unsigned a3 = Qw[(grp + 8) * 68 + kk + tig + 4];
#pragma unroll
            for (int j = 0; j < 8; j++) {
                unsigned b0 = Kc[(j * 8 + grp) * 68 + kk + tig];
                unsigned b1 = Kc[(j * 8 + grp) * 68 + kk + tig + 4];
                asm volatile(
                    "mma.sync.aligned.m16n8k8.row.col.f32.tf32.tf32.f32 "
                    "{%0,%1,%2,%3}, {%4,%5,%6,%7}, {%8,%9}, {%0,%1,%2,%3};"
                    : "+f"(s[j][0]), "+f"(s[j][1]), "+f"(s[j][2]), "+f"(s[j][3])
                    : "r"(a0), "r"(a1), "r"(a2), "r"(a3), "r"(b0), "r"(b1));
            }
        }
#pragma unroll
        for (int j = 0; j < 8; j++) {
            s[j][0] *= 0.125f; s[j][1] *= 0.125f; s[j][2] *= 0.125f; s[j][3] *= 0.125f;
        }

        // ---- online softmax ----
        float mx0 = -INFINITY, mx1 = -INFINITY;
#pragma unroll
        for (int j = 0; j < 8; j++) {
            mx0 = fmaxf(mx0, fmaxf(s[j][0], s[j][1]));
            mx1 = fmaxf(mx1, fmaxf(s[j][2], s[j][3]));
        }
        mx0 = fmaxf(mx0, __shfl_xor_sync(0xffffffffu, mx0, 1));
        mx0 = fmaxf(mx0, __shfl_xor_sync(0xffffffffu, mx0, 2));
        mx1 = fmaxf(mx1, __shfl_xor_sync(0xffffffffu, mx1, 1));
        mx1 = fmaxf(mx1, __shfl_xor_sync(0xffffffffu, mx1, 2));
        float mn0 = fmaxf(m0, mx0), mn1 = fmaxf(m1, mx1);
        float sc0 = __expf(m0 - mn0), sc1 = __expf(m1 - mn1);

        float sum0 = 0.f, sum1 = 0.f;
#pragma unroll
        for (int j = 0; j < 8; j++) {
            float p0 = __expf(s[j][0] - mn0);
            float p1 = __expf(s[j][1] - mn0);
            float p2 = __expf(s[j][2] - mn1);
            float p3 = __expf(s[j][3] - mn1);
            sum0 += p0 + p1; sum1 += p2 + p3;
            Ps[grp * 68 + j * 8 + tig * 2]           = f2tf(p0);
            Ps[grp * 68 + j * 8 + tig * 2 + 1]       = f2tf(p1);
            Ps[(grp + 8) * 68 + j * 8 + tig * 2]     = f2tf(p2);
            Ps[(grp + 8) * 68 + j * 8 + tig * 2 + 1] = f2tf(p3);
        }
        sum0 += __shfl_xor_sync(0xffffffffu, sum0, 1);
        sum0 += __shfl_xor_sync(0xffffffffu, sum0, 2);
        sum1 += __shfl_xor_sync(0xffffffffu, sum1, 1);
        sum1 += __shfl_xor_sync(0xffffffffu, sum1, 2);
        l0 = l0 * sc0 + sum0;
        l1 = l1 * sc1 + sum1;
        m0 = mn0; m1 = mn1;

#pragma unroll
        for (int j = 0; j < 8; j++) {
            o[j][0] *= sc0; o[j][1] *= sc0;
            o[j][2] *= sc1; o[j][3] *= sc1;
        }
        __syncwarp();

        // ---- O += P @ V ----
#pragma unroll
        for (int kk = 0; kk < 64; kk += 8) {
            unsigned a0 = Ps[grp * 68 + kk + tig];
            unsigned a1 = Ps[(grp + 8) * 68 + kk + tig];
            unsigned a2 = Ps[grp * 68 + kk + tig + 4];
            unsigned a3 = Ps[(grp + 8) * 68 + kk + tig + 4];
#pragma unroll
            for (int j = 0; j < 8; j++) {
                unsigned b0 = Vc[(kk + tig) * 72 + j * 8 + grp];
                unsigned b1 = Vc[(kk + tig + 4) * 72 + j * 8 + grp];
                asm volatile(
                    "mma.sync.aligned.m16n8k8.row.col.f32.tf32.tf32.f32 "
                    "{%0,%1,%2,%3}, {%4,%5,%6,%7}, {%8,%9}, {%0,%1,%2,%3};"
                    : "+f"(o[j][0]), "+f"(o[j][1]), "+f"(o[j][2]), "+f"(o[j][3])
                    : "r"(a0), "r"(a1), "r"(a2), "r"(a3), "r"(b0), "r"(b1));
            }
        }
        __syncwarp();
    }

    // ---- normalize + store ----
    float inv0 = 1.f / l0, inv1 = 1.f / l1;
    int row0 = qBase + warp * 16 + grp;
#pragma unroll
    for (int j = 0; j < 8; j++) {
        int col = h * 64 + j * 8 + tig * 2;
        float2 v0 = make_float2(o[j][0] * inv0, o[j][1] * inv0);
        *reinterpret_cast<float2*>(&out[((long)(b * S_ + row0)) * D_ + col]) = v0;
        float2 v1 = make_float2(o[j][2] * inv1, o[j][3] * inv1);
        *reinterpret_cast<float2*>(&out[((long)(b * S_ + row0 + 8)) * D_ + col]) = v1;
    }
}

// ============================================================================
// TF32 tensor-core NT GEMM, 3-stage cp.async pipeline, fused epilogues.
// C[M,N] = epi(alpha * A[M,K] @ B[N,K]^T); M,N %128==0, K%16==0.
// mode 0: plain   mode 1: gelu(v + evec[col])
// mode 2: EX + ada*v   mode 3: EX + ada*(v + evec)   (2048 rows per batch)
// ============================================================================
#define GSTAGES 3
#define GEMM_SMEM (GSTAGES * 128 * 20 * 4 * 2)   // 61440 B

__global__ void __launch_bounds__(256) gemm_nt_tf32(
    const float* __restrict__ A, const float* __restrict__ B, float* __restrict__ C,
    int N, int K, int lda, int ldb, int ldc, float alpha,
    int mode, const float* __restrict__ EX, const float* __restrict__ evec,
    const float* __restrict__ ada, int adaOff)
{
    extern __shared__ unsigned gsm[];
    unsigned* Asm = gsm;                         // [GSTAGES][128][20]
    unsigned* Bsm = gsm + GSTAGES * 128 * 20;

    const int tid   = threadIdx.x;
    const int lane  = tid & 31;
    const int warp  = tid >> 5;
    const int warpM = warp & 1;
    const int warpN = warp >> 1;
    const int grp   = lane >> 2;
    const int tig   = lane & 3;

    const int rowBase = blockIdx.y * 128;
    const int colBase = blockIdx.x * 128;

    const int rowA = tid >> 2;
    const int quad = tid & 3;
    const float* aBase = A + (long)(rowBase + rowA) * lda + quad * 4;
    const float* bBase = B + (long)(colBase + rowA) * ldb + quad * 4;

    float acc[4][4][4];
#pragma unroll
    for (int i = 0; i < 4; i++)
#pragma unroll
        for (int j = 0; j < 4; j++)
#pragma unroll
            for (int t = 0; t < 4; t++) acc[i][j][t] = 0.f;

    const int nCh = K >> 4;

    auto load_chunk = [&](int c, int st) {
        const float* ap = aBase + c * 16;
        const float* bp = bBase + c * 16;
        unsigned* as = Asm + st * 128 * 20;
        unsigned* bs = Bsm + st * 128 * 20;
        cp16(&as[rowA * 20 + quad * 4], ap);
        cp16(&as[(rowA + 64) * 20 + quad * 4], ap + (long)64 * lda);
        cp16(&bs[rowA * 20 + quad * 4], bp);
        cp16(&bs[(rowA + 64) * 20 + quad * 4], bp + (long)64 * ldb);
    };

#pragma unroll
    for (int s = 0; s < GSTAGES - 1; s++) {
        if (s < nCh) load_chunk(s, s);
        CP_COMMIT();
    }

    int st = 0;
    for (int c = 0; c < nCh; c++) {
        CP_WAIT(GSTAGES - 2);
        __syncthreads();

        int nc = c + GSTAGES - 1;
        if (nc < nCh) {
            int nst = nc % GSTAGES;
            load_chunk(nc, nst);
        }
        CP_COMMIT();

        const unsigned* as = Asm + st * 128 * 20;
        const unsigned* bs = Bsm + st * 128 * 20;
#pragma unroll
        for (int kb = 0; kb < 2; kb++) {
            const int kk = kb * 8;
            unsigned af[4][4], bfr[4][2];
#pragma unroll
            for (int i = 0; i < 4; i++) {
                int r0 = warpM * 64 + i * 16 + grp;
                af[i][0] = as[r0 * 20 + kk + tig];
                af[i][1] = as[(r0 + 8) * 20 + kk + tig];
                af[i][2] = as[r0 * 20 + kk + tig + 4];
                af[i][3] = as[(r0 + 8) * 20 + kk + tig + 4];
            }
#pragma unroll
            for (int j = 0; j < 4; j++) {
                int c0 = warpN * 32 + j * 8 + grp;
                bfr[j][0] = bs[c0 * 20 + kk + tig];
                bfr[j][1] = bs[c0 * 20 + kk + tig + 4];
            }
#pragma unroll
            for (int i = 0; i < 4; i++)
#pragma unroll
                for (int j = 0; j < 4; j++) {
                    asm volatile(
                        "mma.sync.aligned.m16n8k8.row.col.f32.tf32.tf32.f32 "
                        "{%0,%1,%2,%3}, {%4,%5,%6,%7}, {%8,%9}, {%0,%1,%2,%3};"
                        : "+f"(acc[i][j][0]), "+f"(acc[i][j][1]),
                          "+f"(acc[i][j][2]), "+f"(acc[i][j][3])
                        : "r"(af[i][0]), "r"(af[i][1]), "r"(af[i][2]), "r"(af[i][3]),
                          "r"(bfr[j][0]), "r"(bfr[j][1]));
                }
        }
        st = (st + 1 == GSTAGES) ? 0 : st + 1;
    }

    // ---- epilogue ----
#pragma unroll
    for (int i = 0; i < 4; i++) {
#pragma unroll
        for (int j = 0; j < 4; j++) {
            long row = rowBase + warpM * 64 + i * 16 + grp;
            int col = colBase + warpN * 32 + j * 8 + tig * 2;
#pragma unroll
            for (int half = 0; half < 2; half++) {
                long r = row + half * 8;
                float v0 = acc[i][j][half * 2] * alpha;
                float v1 = acc[i][j][half * 2 + 1] * alpha;
                if (mode == 1) {
                    v0 = gelu_tanh(v0 + evec[col]);
                    v1 = gelu_tanh(v1 + evec[col + 1]);
                } else if (mode == 2) {
                    int bb = (int)(r >> 11);
                    v0 = EX[r * ldc + col] + ada[bb * 6 * D_ + adaOff + col] * v0;
                    v1 = EX[r * ldc + col + 1] + ada[bb * 6 * D_ + adaOff + col + 1] * v1;
                } else if (mode == 3) {
                    int bb = (int)(r >> 11);
                    v0 = EX[r * ldc + col] + ada[bb * 6 * D_ + adaOff + col] * (v0 + evec[col]);
                    v1 = EX[r * ldc + col + 1] + ada[bb * 6 * D_ + adaOff + col + 1] * (v1 + evec[col + 1]);
                }
                *reinterpret_cast<float2*>(&C[r * ldc + col]) = make_float2(v0, v1);
            }
        }
    }
}

// ---------------- adaLN ----------------
__global__ void __launch_bounds__(256) ada_kernel(
    const float* __restrict__ c, const float* __restrict__ w,
    const float* __restrict__ bias, float* __restrict__ out)
{
    int warp = (blockIdx.x * blockDim.x + threadIdx.x) >> 5;
    int lane = threadIdx.x & 31;
    if (warp >= 6 * D_) return;
    const float* wr = w + (long)warp * D_;
    float s0 = 0.f, s1 = 0.f;
    for (int d = lane; d < D_; d += 32) {
        float wv = wr[d];
        s0 += c[d] * wv;
        s1 += c[D_ + d] * wv;
    }
#pragma unroll
    for (int o = 16; o > 0; o >>= 1) {
        s0 += __shfl_down_sync(0xffffffffu, s0, o);
        s1 += __shfl_down_sync(0xffffffffu, s1, o);
    }
    if (lane == 0) {
        out[warp] = s0 + bias[warp];
        out[6 * D_ + warp] = s1 + bias[warp];
    }
}

// ---------------- LayerNorm + modulate ----------------
__global__ void __launch_bounds__(256) ln_mod_kernel(
    const float* __restrict__ x, const float* __restrict__ w,
    const float* __restrict__ ada, int shOff, int scOff, float* __restrict__ h)
{
    int r = blockIdx.x;
    int b = r >> 11;
    const float* xr = x + (long)r * D_;
    int tid = threadIdx.x;
    float s = 0.f, ss = 0.f;
    float vals[4];
#pragma unroll
    for (int i = 0; i < 4; i++) {
        float v = xr[tid + i * 256];
        vals[i] = v; s += v; ss += v * v;
    }
    __shared__ float rs[256], rss[256];
    rs[tid] = s; rss[tid] = ss;
    __syncthreads();
    for (int st = 128; st > 0; st >>= 1) {
        if (tid < st) { rs[tid] += rs[tid + st]; rss[tid] += rss[tid + st]; }
        __syncthreads();
    }
    float mean = rs[0] * (1.f / D_);
    float var = rss[0] * (1.f / D_) - mean * mean;
    float inv = rsqrtf(var + 1e-5f);
    const float* sh = ada + b * 6 * D_ + shOff;
    const float* sc = ada + b * 6 * D_ + scOff;
#pragma unroll
    for (int i = 0; i < 4; i++) {
        int d = tid + i * 256;
        h[(long)r * D_ + d] = (vals[i] - mean) * inv * w[d] * (1.f + sc[d]) + sh[d];
    }
}

// ---------------- launch ----------------
extern "C" void kernel_launch(void* const* d_in, const int* in_sizes, int n_in,
                              void* d_out, int out_size)
{
    (void)in_sizes; (void)n_in; (void)out_size;
    const float* x       = (const float*)d_in[0];
    const float* c       = (const float*)d_in[3];
    const float* norm1_w = (const float*)d_in[4];
    const float* w_qkv   = (const float*)d_in[5];
    const float* w_out   = (const float*)d_in[6];
    const float* norm2_w = (const float*)d_in[7];
    const float* mlp_w1  = (const float*)d_in[8];
    const float* mlp_b1  = (const float*)d_in[9];
    const float* mlp_w2  = (const float*)d_in[10];
    const float* mlp_b2  = (const float*)d_in[11];
    const float* ada_w   = (const float*)d_in[12];
    const float* ada_b   = (const float*)d_in[13];
    float* out = (float*)d_out;

    float *ada, *h, *qkv, *attn2, *x1, *mlp;
    cudaGetSymbolAddress((void**)&ada,   g_ada);
    cudaGetSymbolAddress((void**)&h,     g_h);
    cudaGetSymbolAddress((void**)&qkv,   g_qkv);
    cudaGetSymbolAddress((void**)&attn2, g_attn2);
    cudaGetSymbolAddress((void**)&x1,    g_x1);
    cudaGetSymbolAddress((void**)&mlp,   g_mlp);

    static int inited = 0;
    if (!inited) {
        cudaFuncSetAttribute(flash_attn, cudaFuncAttributeMaxDynamicSharedMemorySize, FA_SMEM);
        cudaFuncSetAttribute(gemm_nt_tf32, cudaFuncAttributeMaxDynamicSharedMemorySize, GEMM_SMEM);
        inited = 1;
    }

    // 1. adaLN projection
    ada_kernel<<<768, 256>>>(c, ada_w, ada_b, ada);
    // 2. LN1 + modulate
    ln_mod_kernel<<<B_ * S_, 256>>>(x, norm1_w, ada, 0, D_, h);
    // 3. QKV GEMM [4096,1024] @ [3072,1024]^T
    gemm_nt_tf32<<<dim3(24, 32), 256, GEMM_SMEM>>>(h, w_qkv, qkv, 3 * D_, D_,
                                                   D_, D_, 3 * D_, 1.f, 0,
                                                   nullptr, nullptr, nullptr, 0);
    // 4. fused flash attention -> attn2 [B,S,D]
    flash_attn<<<dim3(S_ / 128, B_ * H_), 256, FA_SMEM>>>(qkv, attn2);
    // 5. out-proj + residual1 fused
    gemm_nt_tf32<<<dim3(8, 32), 256, GEMM_SMEM>>>(attn2, w_out, x1, D_, D_,
                                                  D_, D_, D_, 1.f, 2,
                                                  x, nullptr, ada, 2 * D_);
    // 6. LN2 + modulate
    ln_mod_kernel<<<B_ * S_, 256>>>(x1, norm2_w, ada, 3 * D_, 4 * D_, h);
    // 7. MLP1 + bias + gelu fused
    gemm_nt_tf32<<<dim3(32, 32), 256, GEMM_SMEM>>>(h, mlp_w1, mlp, 4 * D_, D_,
                                                   D_, D_, 4 * D_, 1.f, 1,
                                                   nullptr, mlp_b1, nullptr, 0);
    // 8. MLP2 + final residual fused
    gemm_nt_tf32<<<dim3(8, 32), 256, GEMM_SMEM>>>(mlp, mlp_w2, out, D_, 4 * D_,
                                                  4 * D_, 4 * D_, D_, 1.f, 3,
                                                  x1, mlp_b2, ada, 5 * D_);
}

// round 5
// speedup vs baseline: 3.7775x; 1.0961x over previous
#include <cuda_runtime.h>
#include <math.h>

#define B_ 2
#define S_ 2048
#define D_ 1024
#define H_ 16
#define HD_ 64

// ---------------- scratch ----------------
__device__ float g_ada[B_ * 6 * D_];
__device__ float g_h[(size_t)B_ * S_ * D_];
__device__ float g_qkv[(size_t)B_ * S_ * 3 * D_];
__device__ float g_attn2[(size_t)B_ * S_ * D_];
__device__ float g_x1[(size_t)B_ * S_ * D_];
__device__ float g_mlp[(size_t)B_ * S_ * 4 * D_];

__device__ __forceinline__ unsigned f2tf(float f) {
    unsigned u;
    asm("cvt.rna.tf32.f32 %0, %1;" : "=r"(u) : "f"(f));
    return u;
}
// round-to-nearest for tf32: HW truncates low 13 bits, so +0x1000 = RN(ties up)
__device__ __forceinline__ unsigned rnd(unsigned u) { return u + 0x1000u; }

__device__ __forceinline__ float gelu_tanh(float v) {
    float u = 0.7978845608028654f * (v + 0.044715f * v * v * v);
    return 0.5f * v * (1.f + tanhf(u));
}

__device__ __forceinline__ void cp16(void* s, const void* g) {
    unsigned sa = (unsigned)__cvta_generic_to_shared(s);
    asm volatile("cp.async.cg.shared.global [%0], [%1], 16;" :: "r"(sa), "l"(g));
}
#define CP_COMMIT() asm volatile("cp.async.commit_group;")
#define CP_WAIT(n)  asm volatile("cp.async.wait_group %0;" :: "n"(n))

// ============================================================================
// Fused flash attention (tf32 mma, online softmax, cp.async double-buffered KV)
// qkv: [B, S, 3, H, HD] fp32. out: [B, S, H*HD] fp32.
// 512 threads = 16 warps, Q tile 256 rows, 16 q-rows/warp, key tiles of 64.
// smem words: Q[256][68]=17408 | K 2x[64][68]=8704 | V 2x[64][72]=9216 |
//             P 16x[16][68]=17408  -> total 52736 words = 210944 B
// ============================================================================
#define FA_SMEM 210944

__global__ void __launch_bounds__(512) flash_attn(
    const float* __restrict__ qkv, float* __restrict__ out)
{
    extern __shared__ unsigned sm[];
    unsigned* Qs  = sm;                     // [256][68]
    unsigned* Ks  = sm + 17408;             // [2][64][68]
    unsigned* Vs  = sm + 26112;             // [2][64][72]
    unsigned* Psw = sm + 35328;             // 16 x [16][68]

    const int tid  = threadIdx.x;
    const int lane = tid & 31;
    const int warp = tid >> 5;
    const int grp  = lane >> 2;
    const int tig  = lane & 3;
    const int b    = blockIdx.y >> 4;
    const int h    = blockIdx.y & 15;
    const int qBase = blockIdx.x * 256;

    // ---- prologue: Q tile + KV tile 0 via cp.async ----
#pragma unroll
    for (int i = 0; i < 8; i++) {
        int idx = tid + i * 512;            // 0..4095
        int r   = idx >> 4;                 // 0..255
        int qd  = idx & 15;
        cp16(&Qs[r * 68 + qd * 4],
             &qkv[((long)(b * S_ + qBase + r)) * 3072 + h * 64 + qd * 4]);
    }
#pragma unroll
    for (int i = 0; i < 2; i++) {
        int idx = tid + i * 512;            // 0..1023
        int r   = idx >> 4;                 // 0..63
        int qd  = idx & 15;
        const float* base = &qkv[((long)(b * S_ + r)) * 3072 + h * 64 + qd * 4];
        cp16(&Ks[r * 68 + qd * 4], base + 1024);
        cp16(&Vs[r * 72 + qd * 4], base + 2048);
    }
    CP_COMMIT();

    unsigned* Ps = Psw + warp * 16 * 68;
    const unsigned* Qw = Qs + warp * 16 * 68;

    float m0 = -INFINITY, m1 = -INFINITY, l0 = 0.f, l1 = 0.f;
    float o[8][4];
#pragma unroll
    for (int j = 0; j < 8; j++)
#pragma unroll
        for (int t = 0; t < 4; t++) o[j][t] = 0.f;

    const int nT = S_ / 64;
    for (int t = 0; t < nT; t++) {
        CP_WAIT(0);
        __syncthreads();

        // prefetch next KV tile into the other buffer
        if (t + 1 < nT) {
            unsigned* Kn = Ks + ((t + 1) & 1) * 4352;
            unsigned* Vn = Vs + ((t + 1) & 1) * 4608;
            int kt = (t + 1) * 64;
#pragma unroll
            for (int i = 0; i < 2; i++) {
                int idx = tid + i * 512;
                int r   = idx >> 4;
                int qd  = idx & 15;
                const float* base = &qkv[((long)(b * S_ + kt + r)) * 3072 + h * 64 + qd * 4];
                cp16(&Kn[r * 68 + qd * 4], base + 1024);
                cp16(&Vn[r * 72 + qd * 4], base + 2048);
            }
        }
        CP_COMMIT();

        const unsigned* Kc = Ks + (t & 1) * 4352;
        const unsigned* Vc = Vs + (t & 1) * 4608;

        // ---- scores = Q @ K^T ----
        float s[8][4];
#pragma unroll
        for (int j = 0; j < 8; j++)
#pragma unroll
            for (int tt = 0; tt < 4; tt++) s[j][tt] = 0.f;

#pragma unroll
        for (int kk = 0; kk < 64; kk += 8) {
            unsigned a0 = rnd(Qw[grp * 68 + kk + tig]);
            unsigned a1 = rnd(Qw[(grp + 8) * 68 + kk + tig]);
            unsigned a2 = rnd(Qw[grp * 68 + kk + tig + 4]);
            unsigned a3 = rnd(Qw[(grp + 8) * 68 + kk + tig + 4]);
#pragma unroll
            for (int j = 0; j < 8; j++) {
                unsigned b0 = rnd(Kc[(j * 8 + grp) * 68 + kk + tig]);
                unsigned b1 = rnd(Kc[(j * 8 + grp) * 68 + kk + tig + 4]);
                asm volatile(
                    "mma.sync.aligned.m16n8k8.row.col.f32.tf32.tf32.f32 "
                    "{%0,%1,%2,%3}, {%4,%5,%6,%7}, {%8,%9}, {%0,%1,%2,%3};"
                    : "+f"(s[j][0]), "+f"(s[j][1]), "+f"(s[j][2]), "+f"(s[j][3])
                    : "r"(a0), "r"(a1), "r"(a2), "r"(a3), "r"(b0), "r"(b1));
            }
        }
#pragma unroll
        for (int j = 0; j < 8; j++) {
            s[j][0] *= 0.125f; s[j][1] *= 0.125f; s[j][2] *= 0.125f; s[j][3] *= 0.125f;
        }

        // ---- online softmax ----
        float mx0 = -INFINITY, mx1 = -INFINITY;
#pragma unroll
        for (int j = 0; j < 8; j++) {
            mx0 = fmaxf(mx0, fmaxf(s[j][0], s[j][1]));
            mx1 = fmaxf(mx1, fmaxf(s[j][2], s[j][3]));
        }
        mx0 = fmaxf(mx0, __shfl_xor_sync(0xffffffffu, mx0, 1));
        mx0 = fmaxf(mx0, __shfl_xor_sync(0xffffffffu, mx0, 2));
        mx1 = fmaxf(mx1, __shfl_xor_sync(0xffffffffu, mx1, 1));
        mx1 = fmaxf(mx1, __shfl_xor_sync(0xffffffffu, mx1, 2));
        float mn0 = fmaxf(m0, mx0), mn1 = fmaxf(m1, mx1);
        float sc0 = __expf(m0 - mn0), sc1 = __expf(m1 - mn1);

        float sum0 = 0.f, sum1 = 0.f;
#pragma unroll
        for (int j = 0; j < 8; j++) {
            float p0 = __expf(s[j][0] - mn0);
            float p1 = __expf(s[j][1] - mn0);
            float p2 = __expf(s[j][2] - mn1);
            float p3 = __expf(s[j][3] - mn1);
            sum0 += p0 + p1; sum1 += p2 + p3;
            Ps[grp * 68 + j * 8 + tig * 2]           = f2tf(p0);
            Ps[grp * 68 + j * 8 + tig * 2 + 1]       = f2tf(p1);
            Ps[(grp + 8) * 68 + j * 8 + tig * 2]     = f2tf(p2);
            Ps[(grp + 8) * 68 + j * 8 + tig * 2 + 1] = f2tf(p3);
        }
        sum0 += __shfl_xor_sync(0xffffffffu, sum0, 1);
        sum0 += __shfl_xor_sync(0xffffffffu, sum0, 2);
        sum1 += __shfl_xor_sync(0xffffffffu, sum1, 1);
        sum1 += __shfl_xor_sync(0xffffffffu, sum1, 2);
        l0 = l0 * sc0 + sum0;
        l1 = l1 * sc1 + sum1;
        m0 = mn0; m1 = mn1;

#pragma unroll
        for (int j = 0; j < 8; j++) {
            o[j][0] *= sc0; o[j][1] *= sc0;
            o[j][2] *= sc1; o[j][3] *= sc1;
        }
        __syncwarp();

        // ---- O += P @ V ----
#pragma unroll
        for (int kk = 0; kk < 64; kk += 8) {
            unsigned a0 = Ps[grp * 68 + kk + tig];
            unsigned a1 = Ps[(grp + 8) * 68 + kk + tig];
            unsigned a2 = Ps[grp * 68 + kk + tig + 4];
            unsigned a3 = Ps[(grp + 8) * 68 + kk + tig + 4];
#pragma unroll
            for (int j = 0; j < 8; j++) {
                unsigned b0 = rnd(Vc[(kk + tig) * 72 + j * 8 + grp]);
                unsigned b1 = rnd(Vc[(kk + tig + 4) * 72 + j * 8 + grp]);
                asm volatile(
                    "mma.sync.aligned.m16n8k8.row.col.f32.tf32.tf32.f32 "
                    "{%0,%1,%2,%3}, {%4,%5,%6,%7}, {%8,%9}, {%0,%1,%2,%3};"
                    : "+f"(o[j][0]), "+f"(o[j][1]), "+f"(o[j][2]), "+f"(o[j][3])
                    : "r"(a0), "r"(a1), "r"(a2), "r"(a3), "r"(b0), "r"(b1));
            }
        }
        __syncwarp();
    }

    // ---- normalize + store ----
    float inv0 = 1.f / l0, inv1 = 1.f / l1;
    int row0 = qBase + warp * 16 + grp;
#pragma unroll
    for (int j = 0; j < 8; j++) {
        int col = h * 64 + j * 8 + tig * 2;
        float2 v0 = make_float2(o[j][0] * inv0, o[j][1] * inv0);
        *reinterpret_cast<float2*>(&out[((long)(b * S_ + row0)) * D_ + col]) = v0;
        float2 v1 = make_float2(o[j][2] * inv1, o[j][3] * inv1);
        *reinterpret_cast<float2*>(&out[((long)(b * S_ + row0 + 8)) * D_ + col]) = v1;
    }
}

// ============================================================================
// TF32 tensor-core NT GEMM, 3-stage cp.async pipeline, fused epilogues.
// C[M,N] = epi(alpha * A[M,K] @ B[N,K]^T); M,N %128==0, K%16==0.
// mode 0: plain   mode 1: gelu(v + evec[col])
// mode 2: EX + ada*v   mode 3: EX + ada*(v + evec)   (2048 rows per batch)
// ============================================================================
#define GSTAGES 3
#define GEMM_SMEM (GSTAGES * 128 * 20 * 4 * 2)   // 61440 B

__global__ void __launch_bounds__(256) gemm_nt_tf32(
    const float* __restrict__ A, const float* __restrict__ B, float* __restrict__ C,
    int N, int K, int lda, int ldb, int ldc, float alpha,
    int mode, const float* __restrict__ EX, const float* __restrict__ evec,
    const float* __restrict__ ada, int adaOff)
{
    extern __shared__ unsigned gsm[];
    unsigned* Asm = gsm;                         // [GSTAGES][128][20]
    unsigned* Bsm = gsm + GSTAGES * 128 * 20;

    const int tid   = threadIdx.x;
    const int lane  = tid & 31;
    const int warp  = tid >> 5;
    const int warpM = warp & 1;
    const int warpN = warp >> 1;
    const int grp   = lane >> 2;
    const int tig   = lane & 3;

    const int rowBase = blockIdx.y * 128;
    const int colBase = blockIdx.x * 128;

    const int rowA = tid >> 2;
    const int quad = tid & 3;
    const float* aBase = A + (long)(rowBase + rowA) * lda + quad * 4;
    const float* bBase = B + (long)(colBase + rowA) * ldb + quad * 4;

    float acc[4][4][4];
#pragma unroll
    for (int i = 0; i < 4; i++)
#pragma unroll
        for (int j = 0; j < 4; j++)
#pragma unroll
            for (int t = 0; t < 4; t++) acc[i][j][t] = 0.f;

    const int nCh = K >> 4;

    auto load_chunk = [&](int c, int st) {
        const float* ap = aBase + c * 16;
        const float* bp = bBase + c * 16;
        unsigned* as = Asm + st * 128 * 20;
        unsigned* bs = Bsm + st * 128 * 20;
        cp16(&as[rowA * 20 + quad * 4], ap);
        cp16(&as[(rowA + 64) * 20 + quad * 4], ap + (long)64 * lda);
        cp16(&bs[rowA * 20 + quad * 4], bp);
        cp16(&bs[(rowA + 64) * 20 + quad * 4], bp + (long)64 * ldb);
    };

#pragma unroll
    for (int s = 0; s < GSTAGES - 1; s++) {
        if (s < nCh) load_chunk(s, s);
        CP_COMMIT();
    }

    int st = 0;
    for (int c = 0; c < nCh; c++) {
        CP_WAIT(GSTAGES - 2);
        __syncthreads();

        int nc = c + GSTAGES - 1;
        if (nc < nCh) {
            int nst = nc % GSTAGES;
            load_chunk(nc, nst);
        }
        CP_COMMIT();

        const unsigned* as = Asm + st * 128 * 20;
        const unsigned* bs = Bsm + st * 128 * 20;
#pragma unroll
        for (int kb = 0; kb < 2; kb++) {
            const int kk = kb * 8;
            unsigned af[4][4], bfr[4][2];
#pragma unroll
            for (int i = 0; i < 4; i++) {
                int r0 = warpM * 64 + i * 16 + grp;
                af[i][0] = rnd(as[r0 * 20 + kk + tig]);
                af[i][1] = rnd(as[(r0 + 8) * 20 + kk + tig]);
                af[i][2] = rnd(as[r0 * 20 + kk + tig + 4]);
                af[i][3] = rnd(as[(r0 + 8) * 20 + kk + tig + 4]);
            }
#pragma unroll
            for (int j = 0; j < 4; j++) {
                int c0 = warpN * 32 + j * 8 + grp;
                bfr[j][0] = rnd(bs[c0 * 20 + kk + tig]);
                bfr[j][1] = rnd(bs[c0 * 20 + kk + tig + 4]);
            }
#pragma unroll
            for (int i = 0; i < 4; i++)
#pragma unroll
                for (int j = 0; j < 4; j++) {
                    asm volatile(
                        "mma.sync.aligned.m16n8k8.row.col.f32.tf32.tf32.f32 "
                        "{%0,%1,%2,%3}, {%4,%5,%6,%7}, {%8,%9}, {%0,%1,%2,%3};"
                        : "+f"(acc[i][j][0]), "+f"(acc[i][j][1]),
                          "+f"(acc[i][j][2]), "+f"(acc[i][j][3])
                        : "r"(af[i][0]), "r"(af[i][1]), "r"(af[i][2]), "r"(af[i][3]),
                          "r"(bfr[j][0]), "r"(bfr[j][1]));
                }
        }
        st = (st + 1 == GSTAGES) ? 0 : st + 1;
    }

    // ---- epilogue ----
#pragma unroll
    for (int i = 0; i < 4; i++) {
#pragma unroll
        for (int j = 0; j < 4; j++) {
            long row = rowBase + warpM * 64 + i * 16 + grp;
            int col = colBase + warpN * 32 + j * 8 + tig * 2;
#pragma unroll
            for (int half = 0; half < 2; half++) {
                long r = row + half * 8;
                float v0 = acc[i][j][half * 2] * alpha;
                float v1 = acc[i][j][half * 2 + 1] * alpha;
                if (mode == 1) {
                    v0 = gelu_tanh(v0 + evec[col]);
                    v1 = gelu_tanh(v1 + evec[col + 1]);
                } else if (mode == 2) {
                    int bb = (int)(r >> 11);
                    v0 = EX[r * ldc + col] + ada[bb * 6 * D_ + adaOff + col] * v0;
                    v1 = EX[r * ldc + col + 1] + ada[bb * 6 * D_ + adaOff + col + 1] * v1;
                } else if (mode == 3) {
                    int bb = (int)(r >> 11);
                    v0 = EX[r * ldc + col] + ada[bb * 6 * D_ + adaOff + col] * (v0 + evec[col]);
                    v1 = EX[r * ldc + col + 1] + ada[bb * 6 * D_ + adaOff + col + 1] * (v1 + evec[col + 1]);
                }
                *reinterpret_cast<float2*>(&C[r * ldc + col]) = make_float2(v0, v1);
            }
        }
    }
}

// ---------------- adaLN ----------------
__global__ void __launch_bounds__(256) ada_kernel(
    const float* __restrict__ c, const float* __restrict__ w,
    const float* __restrict__ bias, float* __restrict__ out)
{
    int warp = (blockIdx.x * blockDim.x + threadIdx.x) >> 5;
    int lane = threadIdx.x & 31;
    if (warp >= 6 * D_) return;
    const float* wr = w + (long)warp * D_;
    float s0 = 0.f, s1 = 0.f;
    for (int d = lane; d < D_; d += 32) {
        float wv = wr[d];
        s0 += c[d] * wv;
        s1 += c[D_ + d] * wv;
    }
#pragma unroll
    for (int o = 16; o > 0; o >>= 1) {
        s0 += __shfl_down_sync(0xffffffffu, s0, o);
        s1 += __shfl_down_sync(0xffffffffu, s1, o);
    }
    if (lane == 0) {
        out[warp] = s0 + bias[warp];
        out[6 * D_ + warp] = s1 + bias[warp];
    }
}

// ---------------- LayerNorm + modulate ----------------
__global__ void __launch_bounds__(256) ln_mod_kernel(
    const float* __restrict__ x, const float* __restrict__ w,
    const float* __restrict__ ada, int shOff, int scOff, float* __restrict__ h)
{
    int r = blockIdx.x;
    int b = r >> 11;
    const float* xr = x + (long)r * D_;
    int tid = threadIdx.x;
    float s = 0.f, ss = 0.f;
    float vals[4];
#pragma unroll
    for (int i = 0; i < 4; i++) {
        float v = xr[tid + i * 256];
        vals[i] = v; s += v; ss += v * v;
    }
    __shared__ float rs[256], rss[256];
    rs[tid] = s; rss[tid] = ss;
    __syncthreads();
    for (int st = 128; st > 0; st >>= 1) {
        if (tid < st) { rs[tid] += rs[tid + st]; rss[tid] += rss[tid + st]; }
        __syncthreads();
    }
    float mean = rs[0] * (1.f / D_);
    float var = rss[0] * (1.f / D_) - mean * mean;
    float inv = rsqrtf(var + 1e-5f);
    const float* sh = ada + b * 6 * D_ + shOff;
    const float* sc = ada + b * 6 * D_ + scOff;
#pragma unroll
    for (int i = 0; i < 4; i++) {
        int d = tid + i * 256;
        h[(long)r * D_ + d] = (vals[i] - mean) * inv * w[d] * (1.f + sc[d]) + sh[d];
    }
}

// ---------------- launch ----------------
extern "C" void kernel_launch(void* const* d_in, const int* in_sizes, int n_in,
                              void* d_out, int out_size)
{
    (void)in_sizes; (void)n_in; (void)out_size;
    const float* x       = (const float*)d_in[0];
    const float* c       = (const float*)d_in[3];
    const float* norm1_w = (const float*)d_in[4];
    const float* w_qkv   = (const float*)d_in[5];
    const float* w_out   = (const float*)d_in[6];
    const float* norm2_w = (const float*)d_in[7];
    const float* mlp_w1  = (const float*)d_in[8];
    const float* mlp_b1  = (const float*)d_in[9];
    const float* mlp_w2  = (const float*)d_in[10];
    const float* mlp_b2  = (const float*)d_in[11];
    const float* ada_w   = (const float*)d_in[12];
    const float* ada_b   = (const float*)d_in[13];
    float* out = (float*)d_out;

    float *ada, *h, *qkv, *attn2, *x1, *mlp;
    cudaGetSymbolAddress((void**)&ada,   g_ada);
    cudaGetSymbolAddress((void**)&h,     g_h);
    cudaGetSymbolAddress((void**)&qkv,   g_qkv);
    cudaGetSymbolAddress((void**)&attn2, g_attn2);
    cudaGetSymbolAddress((void**)&x1,    g_x1);
    cudaGetSymbolAddress((void**)&mlp,   g_mlp);

    static int inited = 0;
    if (!inited) {
        cudaFuncSetAttribute(flash_attn, cudaFuncAttributeMaxDynamicSharedMemorySize, FA_SMEM);
        cudaFuncSetAttribute(gemm_nt_tf32, cudaFuncAttributeMaxDynamicSharedMemorySize, GEMM_SMEM);
        inited = 1;
    }

    // 1. adaLN projection
    ada_kernel<<<768, 256>>>(c, ada_w, ada_b, ada);
    // 2. LN1 + modulate
    ln_mod_kernel<<<B_ * S_, 256>>>(x, norm1_w, ada, 0, D_, h);
    // 3. QKV GEMM [4096,1024] @ [3072,1024]^T
    gemm_nt_tf32<<<dim3(24, 32), 256, GEMM_SMEM>>>(h, w_qkv, qkv, 3 * D_, D_,
                                                   D_, D_, 3 * D_, 1.f, 0,
                                                   nullptr, nullptr, nullptr, 0);
    // 4. fused flash attention -> attn2 [B,S,D]
    flash_attn<<<dim3(S_ / 256, B_ * H_), 512, FA_SMEM>>>(qkv, attn2);
    // 5. out-proj + residual1 fused
    gemm_nt_tf32<<<dim3(8, 32), 256, GEMM_SMEM>>>(attn2, w_out, x1, D_, D_,
                                                  D_, D_, D_, 1.f, 2,
                                                  x, nullptr, ada, 2 * D_);
    // 6. LN2 + modulate
    ln_mod_kernel<<<B_ * S_, 256>>>(x1, norm2_w, ada, 3 * D_, 4 * D_, h);
    // 7. MLP1 + bias + gelu fused
    gemm_nt_tf32<<<dim3(32, 32), 256, GEMM_SMEM>>>(h, mlp_w1, mlp, 4 * D_, D_,
                                                   D_, D_, 4 * D_, 1.f, 1,
                                                   nullptr, mlp_b1, nullptr, 0);
    // 8. MLP2 + final residual fused
    gemm_nt_tf32<<<dim3(8, 32), 256, GEMM_SMEM>>>(mlp, mlp_w2, out, D_, 4 * D_,
                                                  4 * D_, 4 * D_, D_, 1.f, 3,
                                                  x1, mlp_b2, ada, 5 * D_);
}